// round 4
// baseline (speedup 1.0000x reference)
#include <cuda_runtime.h>
#include <cuda_bf16.h>
#include <math.h>

// ---------------------------------------------------------------------------
// Shapes (fixed for this problem)
// ---------------------------------------------------------------------------
#define T_SEQ   4096
#define C_EMB   768
#define NHEAD   12
#define HDIM    64
#define QKV_N   (3 * C_EMB)   // 2304

// Scratch (no cudaMalloc allowed)
__device__ float g_qkv[T_SEQ * QKV_N];    // [T, 3C]
__device__ float g_att[T_SEQ * C_EMB];    // [T, C]
__device__ float g_wpt[C_EMB * C_EMB];    // W_proj^T

// ---------------------------------------------------------------------------
// tf32 helpers
// ---------------------------------------------------------------------------
__device__ __forceinline__ unsigned f2tf(float x) {
    unsigned r;
    asm("cvt.rna.tf32.f32 %0, %1;" : "=r"(r) : "f"(x));
    return r;
}

__device__ __forceinline__ void mma_tf32(float c[4],
                                         const unsigned a[4],
                                         unsigned b0, unsigned b1) {
    asm volatile(
        "mma.sync.aligned.m16n8k8.row.col.f32.tf32.tf32.f32 "
        "{%0,%1,%2,%3}, {%4,%5,%6,%7}, {%8,%9}, {%0,%1,%2,%3};"
        : "+f"(c[0]), "+f"(c[1]), "+f"(c[2]), "+f"(c[3])
        : "r"(a[0]), "r"(a[1]), "r"(a[2]), "r"(a[3]), "r"(b0), "r"(b1));
}

// ---------------------------------------------------------------------------
// W_proj transpose: g_wpt[k][n] = W_proj[n][k]   (768x768)
// ---------------------------------------------------------------------------
__global__ void transpose768(const float* __restrict__ in,
                             float* __restrict__ out)
{
    __shared__ float t[32][33];
    int x = blockIdx.x * 32 + threadIdx.x;
    int y0 = blockIdx.y * 32;
#pragma unroll
    for (int j = 0; j < 32; j += 8)
        t[threadIdx.y + j][threadIdx.x] = in[(size_t)(y0 + threadIdx.y + j) * C_EMB + x];
    __syncthreads();
    int xo = blockIdx.y * 32 + threadIdx.x;
    int yo0 = blockIdx.x * 32;
#pragma unroll
    for (int j = 0; j < 32; j += 8)
        out[(size_t)(yo0 + threadIdx.y + j) * C_EMB + xo] = t[threadIdx.x][threadIdx.y + j];
}

// ---------------------------------------------------------------------------
// tf32 GEMM: C[M,N] = A[M,K] @ B[K,N] + bias[N]
// 128x128x16 CTA tile, 256 threads / 8 warps, warp tile 32x64.
// Smem double-buffered: one __syncthreads per k-iter.
// ---------------------------------------------------------------------------
#define GBM 128
#define GBN 128
#define GBK 16
#define AS_ST 20
#define BS_ST 136

__global__ void __launch_bounds__(256)
gemm_tf32(const float* __restrict__ A, const float* __restrict__ B,
          const float* __restrict__ bias, float* __restrict__ C,
          int M, int N, int K)
{
    __shared__ float As[2][GBM][AS_ST];
    __shared__ float Bs[2][GBK][BS_ST];

    const int tid  = threadIdx.x;
    const int w    = tid >> 5;
    const int lane = tid & 31;
    const int g    = lane >> 2;
    const int t    = lane & 3;
    const int wm   = (w & 3) * 32;
    const int wn   = (w >> 2) * 64;
    const int m0   = blockIdx.y * GBM;
    const int n0   = blockIdx.x * GBN;

    const int a_rr = tid >> 2;
    const int a_kc = (tid & 3) << 2;
    const int b_kk = tid >> 5;
    const int b_nc = (tid & 31) << 2;

    float4 ra[2], rb[2];

    auto load_tile = [&](int k0) {
#pragma unroll
        for (int i = 0; i < 2; i++) {
            ra[i] = *(const float4*)(A + (size_t)(m0 + a_rr + 64 * i) * K + k0 + a_kc);
            rb[i] = *(const float4*)(B + (size_t)(k0 + b_kk + 8 * i) * N + n0 + b_nc);
        }
    };
    auto store_tile = [&](int buf) {
#pragma unroll
        for (int i = 0; i < 2; i++) {
            float4 va = make_float4(__uint_as_float(f2tf(ra[i].x)),
                                    __uint_as_float(f2tf(ra[i].y)),
                                    __uint_as_float(f2tf(ra[i].z)),
                                    __uint_as_float(f2tf(ra[i].w)));
            *(float4*)&As[buf][a_rr + 64 * i][a_kc] = va;
            float4 vb = make_float4(__uint_as_float(f2tf(rb[i].x)),
                                    __uint_as_float(f2tf(rb[i].y)),
                                    __uint_as_float(f2tf(rb[i].z)),
                                    __uint_as_float(f2tf(rb[i].w)));
            *(float4*)&Bs[buf][b_kk + 8 * i][b_nc] = vb;
        }
    };

    float acc[2][8][4];
#pragma unroll
    for (int mi = 0; mi < 2; mi++)
#pragma unroll
        for (int ni = 0; ni < 8; ni++)
#pragma unroll
            for (int j = 0; j < 4; j++) acc[mi][ni][j] = 0.f;

    load_tile(0);
    store_tile(0);
    __syncthreads();

    const int nk = K / GBK;
    for (int it = 0; it < nk; it++) {
        const int buf = it & 1;
        const bool more = (it + 1) < nk;
        if (more) load_tile((it + 1) * GBK);

#pragma unroll
        for (int ks = 0; ks < 2; ks++) {
            unsigned af[2][4];
#pragma unroll
            for (int mi = 0; mi < 2; mi++) {
                const float* ap = &As[buf][wm + 16 * mi + g][8 * ks + t];
                af[mi][0] = __float_as_uint(ap[0]);
                af[mi][1] = __float_as_uint(ap[8 * AS_ST]);
                af[mi][2] = __float_as_uint(ap[4]);
                af[mi][3] = __float_as_uint(ap[8 * AS_ST + 4]);
            }
#pragma unroll
            for (int ni = 0; ni < 8; ni++) {
                const float* bp = &Bs[buf][8 * ks + t][wn + 8 * ni + g];
                unsigned b0 = __float_as_uint(bp[0]);
                unsigned b1 = __float_as_uint(bp[4 * BS_ST]);
                mma_tf32(acc[0][ni], af[0], b0, b1);
                mma_tf32(acc[1][ni], af[1], b0, b1);
            }
        }
        if (more) store_tile(buf ^ 1);
        __syncthreads();
    }

#pragma unroll
    for (int mi = 0; mi < 2; mi++) {
        int row = m0 + wm + 16 * mi + g;
#pragma unroll
        for (int ni = 0; ni < 8; ni++) {
            int col = n0 + wn + 8 * ni + 2 * t;
            float2 bv = *(const float2*)(bias + col);
            float2 v0 = make_float2(acc[mi][ni][0] + bv.x, acc[mi][ni][1] + bv.y);
            float2 v1 = make_float2(acc[mi][ni][2] + bv.x, acc[mi][ni][3] + bv.y);
            *(float2*)(C + (size_t)row * N + col)       = v0;
            *(float2*)(C + (size_t)(row + 8) * N + col) = v1;
        }
    }
}

// ---------------------------------------------------------------------------
// Flash attention v4: 128-row Q tiles, 8 warps, tf32 mma, causal.
// - double-buffered K/V smem, register-staged prefetch, 1 sync / k-tile
// - P kept in registers, relayout via warp shuffles (no smem round-trip)
// Grid: (T/128, NHEAD), 256 threads.
// Smem: 2 buffers x (64x68 K + 64x72 V) = 71680 B.
// ---------------------------------------------------------------------------
#define KST 68
#define VST 72
#define BUF_F 8960   // floats per buffer (4352 + 4608)

__global__ void __launch_bounds__(256)
attn_kernel(const float* __restrict__ qkv, float* __restrict__ out)
{
    extern __shared__ float sm[];

    const int tid  = threadIdx.x;
    const int w    = tid >> 5;
    const int lane = tid & 31;
    const int g    = lane >> 2;
    const int t    = lane & 3;
    const int h    = blockIdx.y;
    const int qb   = gridDim.x - 1 - blockIdx.x;   // heavy tiles first
    const int q0   = qb * 128;
    const int kb_last = 2 * qb + 1;
    const float scale = 0.125f;
    const int rA = 16 * w + g;

    // ---- Stage Q (scaled, tf32) into buffer-0 region, grab fragments ----
    {
        float* Qtmp = sm;
#pragma unroll
        for (int i = 0; i < 8; i++) {
            int idx = tid + i * 256;             // 0..2047
            int rr = idx >> 4;                   // 0..127
            int d4 = (idx & 15) << 2;
            float4 v = *(const float4*)(qkv + (size_t)(q0 + rr) * QKV_N + h * HDIM + d4);
            float* qp = Qtmp + rr * KST + d4;
            qp[0] = __uint_as_float(f2tf(v.x * scale));
            qp[1] = __uint_as_float(f2tf(v.y * scale));
            qp[2] = __uint_as_float(f2tf(v.z * scale));
            qp[3] = __uint_as_float(f2tf(v.w * scale));
        }
    }
    __syncthreads();

    unsigned qf[8][4];
    {
        const float* qa  = sm + rA * KST;
        const float* qb2 = qa + 8 * KST;
#pragma unroll
        for (int ks = 0; ks < 8; ks++) {
            qf[ks][0] = __float_as_uint(qa [8 * ks + t]);
            qf[ks][1] = __float_as_uint(qb2[8 * ks + t]);
            qf[ks][2] = __float_as_uint(qa [8 * ks + t + 4]);
            qf[ks][3] = __float_as_uint(qb2[8 * ks + t + 4]);
        }
    }
    __syncthreads();   // Qtmp consumed; buffer 0 free for K/V

    // ---- K/V tile load helpers (4 float4 per thread each) ----
    const int kv_rr = tid >> 4;          // base row (0..15), +16*i
    const int kv_d4 = (tid & 15) << 2;

    auto ldK = [&](int k0, float4 rk[4]) {
#pragma unroll
        for (int i = 0; i < 4; i++)
            rk[i] = *(const float4*)(qkv + (size_t)(k0 + kv_rr + 16 * i) * QKV_N
                                     + C_EMB + h * HDIM + kv_d4);
    };
    auto ldV = [&](int k0, float4 rv[4]) {
#pragma unroll
        for (int i = 0; i < 4; i++)
            rv[i] = *(const float4*)(qkv + (size_t)(k0 + kv_rr + 16 * i) * QKV_N
                                     + 2 * C_EMB + h * HDIM + kv_d4);
    };
    auto stK = [&](int b, const float4 rk[4]) {
        float* Ks = sm + b * BUF_F;
#pragma unroll
        for (int i = 0; i < 4; i++) {
            float* p = Ks + (kv_rr + 16 * i) * KST + kv_d4;
            p[0] = __uint_as_float(f2tf(rk[i].x));
            p[1] = __uint_as_float(f2tf(rk[i].y));
            p[2] = __uint_as_float(f2tf(rk[i].z));
            p[3] = __uint_as_float(f2tf(rk[i].w));
        }
    };
    auto stV = [&](int b, const float4 rv[4]) {
        float* Vs = sm + b * BUF_F + 4352;
#pragma unroll
        for (int i = 0; i < 4; i++) {
            float* p = Vs + (kv_rr + 16 * i) * VST + kv_d4;
            p[0] = __uint_as_float(f2tf(rv[i].x));
            p[1] = __uint_as_float(f2tf(rv[i].y));
            p[2] = __uint_as_float(f2tf(rv[i].z));
            p[3] = __uint_as_float(f2tf(rv[i].w));
        }
    };

    // ---- Prologue: tile 0 into buffer 0 ----
    {
        float4 rk[4], rv[4];
        ldK(0, rk); ldV(0, rv);
        stK(0, rk); stV(0, rv);
    }
    __syncthreads();

    float o[8][4];
#pragma unroll
    for (int nb = 0; nb < 8; nb++)
#pragma unroll
        for (int j = 0; j < 4; j++) o[nb][j] = 0.f;
    float mA = -1e30f, mB = -1e30f, lA = 0.f, lB = 0.f;

    for (int kb = 0; kb <= kb_last; kb++) {
        const int cur = kb & 1;
        const bool more = kb < kb_last;
        const float* Ks = sm + cur * BUF_F;
        const float* Vs = Ks + 4352;
        const int dk = kb - 2 * qb;                // >=0 -> diagonal tiles
        const bool active = !(dk == 1 && w < 4);   // fully masked warps skip

        float4 rk[4];
        if (more) ldK(64 * (kb + 1), rk);

        float s[8][4];
        if (active) {
#pragma unroll
            for (int nb = 0; nb < 8; nb++)
#pragma unroll
                for (int j = 0; j < 4; j++) s[nb][j] = 0.f;

#pragma unroll
            for (int ks = 0; ks < 8; ks++) {
#pragma unroll
                for (int nb = 0; nb < 8; nb++) {
                    const float* kp = Ks + (8 * nb + g) * KST + 8 * ks + t;
                    unsigned b0 = __float_as_uint(kp[0]);
                    unsigned b1 = __float_as_uint(kp[4]);
                    mma_tf32(s[nb], qf[ks], b0, b1);
                }
            }

            if (dk >= 0) {
                const int ra = rA - 64 * dk;
                const int rb2 = ra + 8;
#pragma unroll
                for (int nb = 0; nb < 8; nb++) {
                    int c0 = 8 * nb + 2 * t;
                    if (c0     > ra)  s[nb][0] = -1e30f;
                    if (c0 + 1 > ra)  s[nb][1] = -1e30f;
                    if (c0     > rb2) s[nb][2] = -1e30f;
                    if (c0 + 1 > rb2) s[nb][3] = -1e30f;
                }
            }

            // online softmax
            float mxA = s[0][0], mxB = s[0][2];
#pragma unroll
            for (int nb = 0; nb < 8; nb++) {
                mxA = fmaxf(mxA, fmaxf(s[nb][0], s[nb][1]));
                mxB = fmaxf(mxB, fmaxf(s[nb][2], s[nb][3]));
            }
            mxA = fmaxf(mxA, __shfl_xor_sync(0xffffffffu, mxA, 1));
            mxA = fmaxf(mxA, __shfl_xor_sync(0xffffffffu, mxA, 2));
            mxB = fmaxf(mxB, __shfl_xor_sync(0xffffffffu, mxB, 1));
            mxB = fmaxf(mxB, __shfl_xor_sync(0xffffffffu, mxB, 2));

            float nmA = fmaxf(mA, mxA), nmB = fmaxf(mB, mxB);
            float corrA = __expf(mA - nmA), corrB = __expf(mB - nmB);
            mA = nmA; mB = nmB;
            lA *= corrA; lB *= corrB;

#pragma unroll
            for (int nb = 0; nb < 8; nb++) {
                s[nb][0] = __expf(s[nb][0] - mA); lA += s[nb][0];
                s[nb][1] = __expf(s[nb][1] - mA); lA += s[nb][1];
                s[nb][2] = __expf(s[nb][2] - mB); lB += s[nb][2];
                s[nb][3] = __expf(s[nb][3] - mB); lB += s[nb][3];
                o[nb][0] *= corrA; o[nb][1] *= corrA;
                o[nb][2] *= corrB; o[nb][3] *= corrB;
            }
        }

        if (more) stK(cur ^ 1, rk);
        float4 rv[4];
        if (more) ldV(64 * (kb + 1), rv);

        if (active) {
            // P (registers) -> A-fragment via warp shuffles, then PV
            const int src1 = (g << 2) | (t >> 1);
            const int src2 = src1 + 2;
            const bool odd = (t & 1);
#pragma unroll
            for (int ks = 0; ks < 8; ks++) {
                float v00 = __shfl_sync(0xffffffffu, s[ks][0], src1);
                float v01 = __shfl_sync(0xffffffffu, s[ks][1], src1);
                float v02 = __shfl_sync(0xffffffffu, s[ks][0], src2);
                float v12 = __shfl_sync(0xffffffffu, s[ks][1], src2);
                float v20 = __shfl_sync(0xffffffffu, s[ks][2], src1);
                float v21 = __shfl_sync(0xffffffffu, s[ks][3], src1);
                float v22 = __shfl_sync(0xffffffffu, s[ks][2], src2);
                float v32 = __shfl_sync(0xffffffffu, s[ks][3], src2);
                unsigned af[4];
                af[0] = f2tf(odd ? v01 : v00);
                af[1] = f2tf(odd ? v21 : v20);
                af[2] = f2tf(odd ? v12 : v02);
                af[3] = f2tf(odd ? v32 : v22);
#pragma unroll
                for (int nb = 0; nb < 8; nb++) {
                    const float* vp = Vs + (8 * ks + t) * VST + 8 * nb + g;
                    unsigned b0 = __float_as_uint(vp[0]);
                    unsigned b1 = __float_as_uint(vp[4 * VST]);
                    mma_tf32(o[nb], af, b0, b1);
                }
            }
        }

        if (more) stV(cur ^ 1, rv);
        __syncthreads();
    }

    // ---- Finalize ----
    lA += __shfl_xor_sync(0xffffffffu, lA, 1);
    lA += __shfl_xor_sync(0xffffffffu, lA, 2);
    lB += __shfl_xor_sync(0xffffffffu, lB, 1);
    lB += __shfl_xor_sync(0xffffffffu, lB, 2);
    float invA = 1.f / lA, invB = 1.f / lB;

    const int row = q0 + rA;
#pragma unroll
    for (int nb = 0; nb < 8; nb++) {
        int col = h * HDIM + 8 * nb + 2 * t;
        float2 va = make_float2(o[nb][0] * invA, o[nb][1] * invA);
        float2 vb = make_float2(o[nb][2] * invB, o[nb][3] * invB);
        *(float2*)(out + (size_t)row * C_EMB + col)       = va;
        *(float2*)(out + (size_t)(row + 8) * C_EMB + col) = vb;
    }
}

// ---------------------------------------------------------------------------
// Launch
// ---------------------------------------------------------------------------
extern "C" void kernel_launch(void* const* d_in, const int* in_sizes, int n_in,
                              void* d_out, int out_size)
{
    const float* x      = (const float*)d_in[0];
    const float* W_attn = (const float*)d_in[1];
    const float* b_attn = (const float*)d_in[2];
    const float* W_proj = (const float*)d_in[3];
    const float* b_proj = (const float*)d_in[4];
    float* out = (float*)d_out;

    float* qkv = nullptr;
    float* att = nullptr;
    float* wpt = nullptr;
    cudaGetSymbolAddress((void**)&qkv, g_qkv);
    cudaGetSymbolAddress((void**)&att, g_att);
    cudaGetSymbolAddress((void**)&wpt, g_wpt);

    // 0) W_proj^T
    {
        dim3 grid(C_EMB / 32, C_EMB / 32);
        transpose768<<<grid, dim3(32, 8)>>>(W_proj, wpt);
    }

    // 1) qkv = x @ W_attn + b_attn
    {
        dim3 grid(QKV_N / GBN, T_SEQ / GBM);
        gemm_tf32<<<grid, 256>>>(x, W_attn, b_attn, qkv, T_SEQ, QKV_N, C_EMB);
    }

    // 2) flash attention (tf32 mma, 128-row q-tiles)
    {
        size_t smem = (size_t)(2 * BUF_F) * sizeof(float);   // 71680
        cudaFuncSetAttribute(attn_kernel,
                             cudaFuncAttributeMaxDynamicSharedMemorySize,
                             (int)smem);
        dim3 grid(T_SEQ / 128, NHEAD);
        attn_kernel<<<grid, 256, smem>>>(qkv, att);
    }

    // 3) out = att @ W_proj^T + b_proj
    {
        dim3 grid(C_EMB / GBN, T_SEQ / GBM);
        gemm_tf32<<<grid, 256>>>(att, wpt, b_proj, out, T_SEQ, C_EMB, C_EMB);
    }
}

// round 7
// speedup vs baseline: 1.1354x; 1.1354x over previous
#include <cuda_runtime.h>
#include <cuda_bf16.h>
#include <math.h>

// ---------------------------------------------------------------------------
// Shapes (fixed for this problem)
// ---------------------------------------------------------------------------
#define T_SEQ   4096
#define C_EMB   768
#define NHEAD   12
#define HDIM    64
#define QKV_N   (3 * C_EMB)   // 2304

// Scratch (no cudaMalloc allowed)
__device__ float g_qkv[T_SEQ * QKV_N];    // [T, 3C]
__device__ float g_att[T_SEQ * C_EMB];    // [T, C]
__device__ float g_wpt[C_EMB * C_EMB];    // W_proj^T

// ---------------------------------------------------------------------------
// tf32 helpers
// ---------------------------------------------------------------------------
__device__ __forceinline__ unsigned f2tf(float x) {
    unsigned r;
    asm("cvt.rna.tf32.f32 %0, %1;" : "=r"(r) : "f"(x));
    return r;
}

__device__ __forceinline__ void mma_tf32(float c[4],
                                         const unsigned a[4],
                                         unsigned b0, unsigned b1) {
    asm volatile(
        "mma.sync.aligned.m16n8k8.row.col.f32.tf32.tf32.f32 "
        "{%0,%1,%2,%3}, {%4,%5,%6,%7}, {%8,%9}, {%0,%1,%2,%3};"
        : "+f"(c[0]), "+f"(c[1]), "+f"(c[2]), "+f"(c[3])
        : "r"(a[0]), "r"(a[1]), "r"(a[2]), "r"(a[3]), "r"(b0), "r"(b1));
}

// ---------------------------------------------------------------------------
// W_proj transpose: g_wpt[k][n] = W_proj[n][k]   (768x768)
// ---------------------------------------------------------------------------
__global__ void transpose768(const float* __restrict__ in,
                             float* __restrict__ out)
{
    __shared__ float t[32][33];
    int x = blockIdx.x * 32 + threadIdx.x;
    int y0 = blockIdx.y * 32;
#pragma unroll
    for (int j = 0; j < 32; j += 8)
        t[threadIdx.y + j][threadIdx.x] = in[(size_t)(y0 + threadIdx.y + j) * C_EMB + x];
    __syncthreads();
    int xo = blockIdx.y * 32 + threadIdx.x;
    int yo0 = blockIdx.x * 32;
#pragma unroll
    for (int j = 0; j < 32; j += 8)
        out[(size_t)(yo0 + threadIdx.y + j) * C_EMB + xo] = t[threadIdx.x][threadIdx.y + j];
}

// ---------------------------------------------------------------------------
// tf32 GEMM: C[M,N] = A[M,K] @ B[K,N] + bias[N]
// CTA tile (64*MI)x128x16, 256 threads / 8 warps, warp tile (16*MI)x64.
// As: [m][k] stride 20 ; Bs: [k][n] stride 136 (both conflict-free frag loads)
// ---------------------------------------------------------------------------
#define GBN 128
#define GBK 16
#define AS_ST 20
#define BS_ST 136

template <int MI>
__global__ void __launch_bounds__(256)
gemm_tf32(const float* __restrict__ A, const float* __restrict__ B,
          const float* __restrict__ bias, float* __restrict__ C,
          int M, int N, int K)
{
    __shared__ float As[64 * MI][AS_ST];
    __shared__ float Bs[GBK][BS_ST];

    const int tid  = threadIdx.x;
    const int w    = tid >> 5;
    const int lane = tid & 31;
    const int g    = lane >> 2;
    const int t    = lane & 3;
    const int wm   = (w & 3) * 16 * MI;
    const int wn   = (w >> 2) * 64;
    const int m0   = blockIdx.y * 64 * MI;
    const int n0   = blockIdx.x * GBN;

    const int a_rr = tid >> 2;
    const int a_kc = (tid & 3) << 2;
    const int b_kk = tid >> 5;
    const int b_nc = (tid & 31) << 2;

    float4 ra[MI], rb[2];

    auto load_tile = [&](int k0) {
#pragma unroll
        for (int i = 0; i < MI; i++)
            ra[i] = *(const float4*)(A + (size_t)(m0 + a_rr + 64 * i) * K + k0 + a_kc);
#pragma unroll
        for (int i = 0; i < 2; i++)
            rb[i] = *(const float4*)(B + (size_t)(k0 + b_kk + 8 * i) * N + n0 + b_nc);
    };
    auto store_tile = [&]() {
#pragma unroll
        for (int i = 0; i < MI; i++) {
            float4 va = make_float4(__uint_as_float(f2tf(ra[i].x)),
                                    __uint_as_float(f2tf(ra[i].y)),
                                    __uint_as_float(f2tf(ra[i].z)),
                                    __uint_as_float(f2tf(ra[i].w)));
            *(float4*)&As[a_rr + 64 * i][a_kc] = va;
        }
#pragma unroll
        for (int i = 0; i < 2; i++) {
            float4 vb = make_float4(__uint_as_float(f2tf(rb[i].x)),
                                    __uint_as_float(f2tf(rb[i].y)),
                                    __uint_as_float(f2tf(rb[i].z)),
                                    __uint_as_float(f2tf(rb[i].w)));
            *(float4*)&Bs[b_kk + 8 * i][b_nc] = vb;
        }
    };

    float acc[MI][8][4];
#pragma unroll
    for (int mi = 0; mi < MI; mi++)
#pragma unroll
        for (int ni = 0; ni < 8; ni++)
#pragma unroll
            for (int j = 0; j < 4; j++) acc[mi][ni][j] = 0.f;

    load_tile(0);
    store_tile();
    __syncthreads();

    for (int k0 = 0; k0 < K; k0 += GBK) {
        const bool more = (k0 + GBK) < K;
        if (more) load_tile(k0 + GBK);

#pragma unroll
        for (int ks = 0; ks < 2; ks++) {
            unsigned af[MI][4];
#pragma unroll
            for (int mi = 0; mi < MI; mi++) {
                const float* ap = &As[wm + 16 * mi + g][8 * ks + t];
                af[mi][0] = __float_as_uint(ap[0]);
                af[mi][1] = __float_as_uint(ap[8 * AS_ST]);
                af[mi][2] = __float_as_uint(ap[4]);
                af[mi][3] = __float_as_uint(ap[8 * AS_ST + 4]);
            }
#pragma unroll
            for (int ni = 0; ni < 8; ni++) {
                const float* bp = &Bs[8 * ks + t][wn + 8 * ni + g];
                unsigned b0 = __float_as_uint(bp[0]);
                unsigned b1 = __float_as_uint(bp[4 * BS_ST]);
#pragma unroll
                for (int mi = 0; mi < MI; mi++)
                    mma_tf32(acc[mi][ni], af[mi], b0, b1);
            }
        }
        __syncthreads();
        if (more) { store_tile(); __syncthreads(); }
    }

#pragma unroll
    for (int mi = 0; mi < MI; mi++) {
        int row = m0 + wm + 16 * mi + g;
#pragma unroll
        for (int ni = 0; ni < 8; ni++) {
            int col = n0 + wn + 8 * ni + 2 * t;
            float2 bv = *(const float2*)(bias + col);
            float2 v0 = make_float2(acc[mi][ni][0] + bv.x, acc[mi][ni][1] + bv.y);
            float2 v1 = make_float2(acc[mi][ni][2] + bv.x, acc[mi][ni][3] + bv.y);
            *(float2*)(C + (size_t)row * N + col)       = v0;
            *(float2*)(C + (size_t)(row + 8) * N + col) = v1;
        }
    }
}

// ---------------------------------------------------------------------------
// Flash attention v6: 64-row Q tiles, 128 threads, tf32 mma, causal.
// - register prefetch: K at iter top (hidden behind S), V mid-iter (behind PV)
// - P relayout via warp shuffles (no smem round-trip), 2 syncs per k-tile
// Smem: 64x68 (K, also Q staging) + 64x72 (V) = 35840 B.
// ---------------------------------------------------------------------------
#define KST 68
#define VST 72

__global__ void __launch_bounds__(128)
attn_kernel(const float* __restrict__ qkv, float* __restrict__ out)
{
    extern __shared__ float sm[];
    float* Ks = sm;                 // also Q staging at start
    float* Vs = sm + 64 * KST;

    const int tid  = threadIdx.x;
    const int w    = tid >> 5;
    const int lane = tid & 31;
    const int g    = lane >> 2;
    const int t    = lane & 3;
    const int h    = blockIdx.y;
    const int qb   = gridDim.x - 1 - blockIdx.x;   // heavy tiles first
    const int q0   = qb * 64;
    const float scale = 0.125f;
    const int rA   = 16 * w + g;

    const int kv_rr = tid >> 4;
    const int kv_d4 = (tid & 15) << 2;

    // ---- Stage Q (scaled, tf32) into Ks region; grab fragments ----
#pragma unroll
    for (int i = 0; i < 8; i++) {
        int idx = tid + i * 128;
        int rr = idx >> 4;
        int d4 = (idx & 15) << 2;
        float4 v = *(const float4*)(qkv + (size_t)(q0 + rr) * QKV_N + h * HDIM + d4);
        float* qp = Ks + rr * KST + d4;
        qp[0] = __uint_as_float(f2tf(v.x * scale));
        qp[1] = __uint_as_float(f2tf(v.y * scale));
        qp[2] = __uint_as_float(f2tf(v.z * scale));
        qp[3] = __uint_as_float(f2tf(v.w * scale));
    }
    __syncthreads();

    unsigned qf[8][4];
    {
        const float* qa  = Ks + rA * KST;
        const float* qb2 = qa + 8 * KST;
#pragma unroll
        for (int ks = 0; ks < 8; ks++) {
            qf[ks][0] = __float_as_uint(qa [8 * ks + t]);
            qf[ks][1] = __float_as_uint(qb2[8 * ks + t]);
            qf[ks][2] = __float_as_uint(qa [8 * ks + t + 4]);
            qf[ks][3] = __float_as_uint(qb2[8 * ks + t + 4]);
        }
    }
    __syncthreads();   // Q staging consumed; Ks free

    // ---- K/V load/store helpers ----
    auto ldK = [&](int k0, float4 rk[8]) {
#pragma unroll
        for (int i = 0; i < 8; i++) {
            int rr = kv_rr + 8 * i;
            rk[i] = *(const float4*)(qkv + (size_t)(k0 + rr) * QKV_N
                                     + C_EMB + h * HDIM + kv_d4);
        }
    };
    auto ldV = [&](int k0, float4 rv[8]) {
#pragma unroll
        for (int i = 0; i < 8; i++) {
            int rr = kv_rr + 8 * i;
            rv[i] = *(const float4*)(qkv + (size_t)(k0 + rr) * QKV_N
                                     + 2 * C_EMB + h * HDIM + kv_d4);
        }
    };
    auto stK = [&](const float4 rk[8]) {
#pragma unroll
        for (int i = 0; i < 8; i++) {
            float* p = Ks + (kv_rr + 8 * i) * KST + kv_d4;
            p[0] = __uint_as_float(f2tf(rk[i].x));
            p[1] = __uint_as_float(f2tf(rk[i].y));
            p[2] = __uint_as_float(f2tf(rk[i].z));
            p[3] = __uint_as_float(f2tf(rk[i].w));
        }
    };
    auto stV = [&](const float4 rv[8]) {
#pragma unroll
        for (int i = 0; i < 8; i++) {
            float* p = Vs + (kv_rr + 8 * i) * VST + kv_d4;
            p[0] = __uint_as_float(f2tf(rv[i].x));
            p[1] = __uint_as_float(f2tf(rv[i].y));
            p[2] = __uint_as_float(f2tf(rv[i].z));
            p[3] = __uint_as_float(f2tf(rv[i].w));
        }
    };

    // ---- Prologue: tile 0 into smem ----
    {
        float4 r0[8];
        ldK(0, r0); stK(r0);
        ldV(0, r0); stV(r0);
    }
    __syncthreads();

    float o[8][4];
#pragma unroll
    for (int nb = 0; nb < 8; nb++)
#pragma unroll
        for (int j = 0; j < 4; j++) o[nb][j] = 0.f;
    float mA = -1e30f, mB = -1e30f, lA = 0.f, lB = 0.f;

    const int src1 = (g << 2) | (t >> 1);
    const int src2 = src1 + 2;
    const bool odd = (t & 1);

    for (int kb = 0; kb <= qb; kb++) {
        const bool more = kb < qb;

        float4 rpf[8];
        if (more) ldK(64 * (kb + 1), rpf);

        // ---- S = Q K^T ----
        float s[8][4];
#pragma unroll
        for (int nb = 0; nb < 8; nb++)
#pragma unroll
            for (int j = 0; j < 4; j++) s[nb][j] = 0.f;

#pragma unroll
        for (int ks = 0; ks < 8; ks++) {
#pragma unroll
            for (int nb = 0; nb < 8; nb++) {
                const float* kp = Ks + (8 * nb + g) * KST + 8 * ks + t;
                unsigned b0 = __float_as_uint(kp[0]);
                unsigned b1 = __float_as_uint(kp[4]);
                mma_tf32(s[nb], qf[ks], b0, b1);
            }
        }

        if (kb == qb) {   // diagonal: causal mask
            const int rowB = rA + 8;
#pragma unroll
            for (int nb = 0; nb < 8; nb++) {
                int c0 = 8 * nb + 2 * t;
                if (c0     > rA)   s[nb][0] = -1e30f;
                if (c0 + 1 > rA)   s[nb][1] = -1e30f;
                if (c0     > rowB) s[nb][2] = -1e30f;
                if (c0 + 1 > rowB) s[nb][3] = -1e30f;
            }
        }

        // ---- Online softmax ----
        float mxA = s[0][0], mxB = s[0][2];
#pragma unroll
        for (int nb = 0; nb < 8; nb++) {
            mxA = fmaxf(mxA, fmaxf(s[nb][0], s[nb][1]));
            mxB = fmaxf(mxB, fmaxf(s[nb][2], s[nb][3]));
        }
        mxA = fmaxf(mxA, __shfl_xor_sync(0xffffffffu, mxA, 1));
        mxA = fmaxf(mxA, __shfl_xor_sync(0xffffffffu, mxA, 2));
        mxB = fmaxf(mxB, __shfl_xor_sync(0xffffffffu, mxB, 1));
        mxB = fmaxf(mxB, __shfl_xor_sync(0xffffffffu, mxB, 2));

        float nmA = fmaxf(mA, mxA), nmB = fmaxf(mB, mxB);
        float corrA = __expf(mA - nmA), corrB = __expf(mB - nmB);
        mA = nmA; mB = nmB;
        lA *= corrA; lB *= corrB;

#pragma unroll
        for (int nb = 0; nb < 8; nb++) {
            s[nb][0] = __expf(s[nb][0] - mA); lA += s[nb][0];
            s[nb][1] = __expf(s[nb][1] - mA); lA += s[nb][1];
            s[nb][2] = __expf(s[nb][2] - mB); lB += s[nb][2];
            s[nb][3] = __expf(s[nb][3] - mB); lB += s[nb][3];
            o[nb][0] *= corrA; o[nb][1] *= corrA;
            o[nb][2] *= corrB; o[nb][3] *= corrB;
        }

        __syncthreads();          // all warps done reading Ks
        if (more) {
            stK(rpf);             // K(kb+1) -> Ks
            ldV(64 * (kb + 1), rpf);
        }

        // ---- P relayout (shuffles) + O += P V ----
#pragma unroll
        for (int ks = 0; ks < 8; ks++) {
            float v00 = __shfl_sync(0xffffffffu, s[ks][0], src1);
            float v01 = __shfl_sync(0xffffffffu, s[ks][1], src1);
            float v02 = __shfl_sync(0xffffffffu, s[ks][0], src2);
            float v12 = __shfl_sync(0xffffffffu, s[ks][1], src2);
            float v20 = __shfl_sync(0xffffffffu, s[ks][2], src1);
            float v21 = __shfl_sync(0xffffffffu, s[ks][3], src1);
            float v22 = __shfl_sync(0xffffffffu, s[ks][2], src2);
            float v32 = __shfl_sync(0xffffffffu, s[ks][3], src2);
            unsigned af[4];
            af[0] = f2tf(odd ? v01 : v00);
            af[1] = f2tf(odd ? v21 : v20);
            af[2] = f2tf(odd ? v12 : v02);
            af[3] = f2tf(odd ? v32 : v22);
#pragma unroll
            for (int nb = 0; nb < 8; nb++) {
                const float* vp = Vs + (8 * ks + t) * VST + 8 * nb + g;
                unsigned b0 = __float_as_uint(vp[0]);
                unsigned b1 = __float_as_uint(vp[4 * VST]);
                mma_tf32(o[nb], af, b0, b1);
            }
        }

        __syncthreads();          // all warps done reading Vs
        if (more) stV(rpf);       // V(kb+1) -> Vs (consumed after next sync)
    }

    // ---- Finalize ----
    lA += __shfl_xor_sync(0xffffffffu, lA, 1);
    lA += __shfl_xor_sync(0xffffffffu, lA, 2);
    lB += __shfl_xor_sync(0xffffffffu, lB, 1);
    lB += __shfl_xor_sync(0xffffffffu, lB, 2);
    float invA = 1.f / lA, invB = 1.f / lB;

    const int row = q0 + rA;
#pragma unroll
    for (int nb = 0; nb < 8; nb++) {
        int col = h * HDIM + 8 * nb + 2 * t;
        float2 va = make_float2(o[nb][0] * invA, o[nb][1] * invA);
        float2 vb = make_float2(o[nb][2] * invB, o[nb][3] * invB);
        *(float2*)(out + (size_t)row * C_EMB + col)       = va;
        *(float2*)(out + (size_t)(row + 8) * C_EMB + col) = vb;
    }
}

// ---------------------------------------------------------------------------
// Launch
// ---------------------------------------------------------------------------
extern "C" void kernel_launch(void* const* d_in, const int* in_sizes, int n_in,
                              void* d_out, int out_size)
{
    const float* x      = (const float*)d_in[0];
    const float* W_attn = (const float*)d_in[1];
    const float* b_attn = (const float*)d_in[2];
    const float* W_proj = (const float*)d_in[3];
    const float* b_proj = (const float*)d_in[4];
    float* out = (float*)d_out;

    float* qkv = nullptr;
    float* att = nullptr;
    float* wpt = nullptr;
    cudaGetSymbolAddress((void**)&qkv, g_qkv);
    cudaGetSymbolAddress((void**)&att, g_att);
    cudaGetSymbolAddress((void**)&wpt, g_wpt);

    // 0) W_proj^T
    {
        dim3 grid(C_EMB / 32, C_EMB / 32);
        transpose768<<<grid, dim3(32, 8)>>>(W_proj, wpt);
    }

    // 1) qkv = x @ W_attn + b_attn  (128x128 tiles, grid 18x32)
    {
        dim3 grid(QKV_N / GBN, T_SEQ / 128);
        gemm_tf32<2><<<grid, 256>>>(x, W_attn, b_attn, qkv, T_SEQ, QKV_N, C_EMB);
    }

    // 2) flash attention
    {
        size_t smem = (size_t)(64 * KST + 64 * VST) * sizeof(float);   // 35840
        cudaFuncSetAttribute(attn_kernel,
                             cudaFuncAttributeMaxDynamicSharedMemorySize,
                             (int)smem);
        dim3 grid(T_SEQ / 64, NHEAD);
        attn_kernel<<<grid, 128, smem>>>(qkv, att);
    }

    // 3) out = att @ W_proj^T + b_proj  (64x128 tiles, grid 6x64 = 384 CTAs)
    {
        dim3 grid(C_EMB / GBN, T_SEQ / 64);
        gemm_tf32<1><<<grid, 256>>>(att, wpt, b_proj, out, T_SEQ, C_EMB, C_EMB);
    }
}

// round 9
// speedup vs baseline: 1.6648x; 1.4662x over previous
#include <cuda_runtime.h>
#include <cuda_fp16.h>
#include <math.h>
#include <stdint.h>

// ---------------------------------------------------------------------------
// Shapes (fixed)
// ---------------------------------------------------------------------------
#define T_SEQ   4096
#define C_EMB   768
#define NHEAD   12
#define HDIM    64
#define QKV_N   (3 * C_EMB)   // 2304

// Scratch (no cudaMalloc allowed)
__device__ float g_qkv[T_SEQ * QKV_N];    // [T, 3C] fp32
__device__ float g_att[T_SEQ * C_EMB];    // [T, C] fp32
__device__ float g_wpt[C_EMB * C_EMB];    // W_proj^T fp32

// ---------------------------------------------------------------------------
// tf32 helpers (GEMMs — unchanged from R7)
// ---------------------------------------------------------------------------
__device__ __forceinline__ unsigned f2tf(float x) {
    unsigned r;
    asm("cvt.rna.tf32.f32 %0, %1;" : "=r"(r) : "f"(x));
    return r;
}

__device__ __forceinline__ void mma_tf32(float c[4],
                                         const unsigned a[4],
                                         unsigned b0, unsigned b1) {
    asm volatile(
        "mma.sync.aligned.m16n8k8.row.col.f32.tf32.tf32.f32 "
        "{%0,%1,%2,%3}, {%4,%5,%6,%7}, {%8,%9}, {%0,%1,%2,%3};"
        : "+f"(c[0]), "+f"(c[1]), "+f"(c[2]), "+f"(c[3])
        : "r"(a[0]), "r"(a[1]), "r"(a[2]), "r"(a[3]), "r"(b0), "r"(b1));
}

// ---------------------------------------------------------------------------
// fp16 helpers (attention)
// ---------------------------------------------------------------------------
__device__ __forceinline__ uint32_t smem_u32(const void* p) {
    uint32_t a;
    asm("{ .reg .u64 t; cvta.to.shared.u64 t, %1; cvt.u32.u64 %0, t; }"
        : "=r"(a) : "l"(p));
    return a;
}

__device__ __forceinline__ uint32_t pack2(float x, float y) {
    __half2 h = __float22half2_rn(make_float2(x, y));
    return *reinterpret_cast<uint32_t*>(&h);
}

__device__ __forceinline__ void mma_f16(float c[4], const uint32_t a[4],
                                        uint32_t b0, uint32_t b1) {
    asm volatile(
        "mma.sync.aligned.m16n8k16.row.col.f32.f16.f16.f32 "
        "{%0,%1,%2,%3}, {%4,%5,%6,%7}, {%8,%9}, {%0,%1,%2,%3};"
        : "+f"(c[0]), "+f"(c[1]), "+f"(c[2]), "+f"(c[3])
        : "r"(a[0]), "r"(a[1]), "r"(a[2]), "r"(a[3]), "r"(b0), "r"(b1));
}

__device__ __forceinline__ void ldsm_x4(uint32_t r[4], uint32_t addr) {
    asm volatile("ldmatrix.sync.aligned.m8n8.x4.shared.b16 {%0,%1,%2,%3}, [%4];"
                 : "=r"(r[0]), "=r"(r[1]), "=r"(r[2]), "=r"(r[3]) : "r"(addr));
}
__device__ __forceinline__ void ldsm_x4_t(uint32_t r[4], uint32_t addr) {
    asm volatile("ldmatrix.sync.aligned.m8n8.x4.trans.shared.b16 {%0,%1,%2,%3}, [%4];"
                 : "=r"(r[0]), "=r"(r[1]), "=r"(r[2]), "=r"(r[3]) : "r"(addr));
}

// ---------------------------------------------------------------------------
// W_proj transpose (unchanged from R7)
// ---------------------------------------------------------------------------
__global__ void transpose768(const float* __restrict__ in,
                             float* __restrict__ out)
{
    __shared__ float t[32][33];
    int x = blockIdx.x * 32 + threadIdx.x;
    int y0 = blockIdx.y * 32;
#pragma unroll
    for (int j = 0; j < 32; j += 8)
        t[threadIdx.y + j][threadIdx.x] = in[(size_t)(y0 + threadIdx.y + j) * C_EMB + x];
    __syncthreads();
    int xo = blockIdx.y * 32 + threadIdx.x;
    int yo0 = blockIdx.x * 32;
#pragma unroll
    for (int j = 0; j < 32; j += 8)
        out[(size_t)(yo0 + threadIdx.y + j) * C_EMB + xo] = t[threadIdx.x][threadIdx.y + j];
}

// ---------------------------------------------------------------------------
// tf32 GEMM (verbatim R7): C[M,N] = A[M,K] @ B[K,N] + bias[N]
// ---------------------------------------------------------------------------
#define GBN 128
#define GBK 16
#define AS_ST 20
#define BS_ST 136

template <int MI>
__global__ void __launch_bounds__(256)
gemm_tf32(const float* __restrict__ A, const float* __restrict__ B,
          const float* __restrict__ bias, float* __restrict__ C,
          int M, int N, int K)
{
    __shared__ float As[64 * MI][AS_ST];
    __shared__ float Bs[GBK][BS_ST];

    const int tid  = threadIdx.x;
    const int w    = tid >> 5;
    const int lane = tid & 31;
    const int g    = lane >> 2;
    const int t    = lane & 3;
    const int wm   = (w & 3) * 16 * MI;
    const int wn   = (w >> 2) * 64;
    const int m0   = blockIdx.y * 64 * MI;
    const int n0   = blockIdx.x * GBN;

    const int a_rr = tid >> 2;
    const int a_kc = (tid & 3) << 2;
    const int b_kk = tid >> 5;
    const int b_nc = (tid & 31) << 2;

    float4 ra[MI], rb[2];

    auto load_tile = [&](int k0) {
#pragma unroll
        for (int i = 0; i < MI; i++)
            ra[i] = *(const float4*)(A + (size_t)(m0 + a_rr + 64 * i) * K + k0 + a_kc);
#pragma unroll
        for (int i = 0; i < 2; i++)
            rb[i] = *(const float4*)(B + (size_t)(k0 + b_kk + 8 * i) * N + n0 + b_nc);
    };
    auto store_tile = [&]() {
#pragma unroll
        for (int i = 0; i < MI; i++) {
            float4 va = make_float4(__uint_as_float(f2tf(ra[i].x)),
                                    __uint_as_float(f2tf(ra[i].y)),
                                    __uint_as_float(f2tf(ra[i].z)),
                                    __uint_as_float(f2tf(ra[i].w)));
            *(float4*)&As[a_rr + 64 * i][a_kc] = va;
        }
#pragma unroll
        for (int i = 0; i < 2; i++) {
            float4 vb = make_float4(__uint_as_float(f2tf(rb[i].x)),
                                    __uint_as_float(f2tf(rb[i].y)),
                                    __uint_as_float(f2tf(rb[i].z)),
                                    __uint_as_float(f2tf(rb[i].w)));
            *(float4*)&Bs[b_kk + 8 * i][b_nc] = vb;
        }
    };

    float acc[MI][8][4];
#pragma unroll
    for (int mi = 0; mi < MI; mi++)
#pragma unroll
        for (int ni = 0; ni < 8; ni++)
#pragma unroll
            for (int j = 0; j < 4; j++) acc[mi][ni][j] = 0.f;

    load_tile(0);
    store_tile();
    __syncthreads();

    for (int k0 = 0; k0 < K; k0 += GBK) {
        const bool more = (k0 + GBK) < K;
        if (more) load_tile(k0 + GBK);

#pragma unroll
        for (int ks = 0; ks < 2; ks++) {
            unsigned af[MI][4];
#pragma unroll
            for (int mi = 0; mi < MI; mi++) {
                const float* ap = &As[wm + 16 * mi + g][8 * ks + t];
                af[mi][0] = __float_as_uint(ap[0]);
                af[mi][1] = __float_as_uint(ap[8 * AS_ST]);
                af[mi][2] = __float_as_uint(ap[4]);
                af[mi][3] = __float_as_uint(ap[8 * AS_ST + 4]);
            }
#pragma unroll
            for (int ni = 0; ni < 8; ni++) {
                const float* bp = &Bs[8 * ks + t][wn + 8 * ni + g];
                unsigned b0 = __float_as_uint(bp[0]);
                unsigned b1 = __float_as_uint(bp[4 * BS_ST]);
#pragma unroll
                for (int mi = 0; mi < MI; mi++)
                    mma_tf32(acc[mi][ni], af[mi], b0, b1);
            }
        }
        __syncthreads();
        if (more) { store_tile(); __syncthreads(); }
    }

#pragma unroll
    for (int mi = 0; mi < MI; mi++) {
        int row = m0 + wm + 16 * mi + g;
#pragma unroll
        for (int ni = 0; ni < 8; ni++) {
            int col = n0 + wn + 8 * ni + 2 * t;
            float2 bv = *(const float2*)(bias + col);
            float2 v0 = make_float2(acc[mi][ni][0] + bv.x, acc[mi][ni][1] + bv.y);
            float2 v1 = make_float2(acc[mi][ni][2] + bv.x, acc[mi][ni][3] + bv.y);
            *(float2*)(C + (size_t)row * N + col)       = v0;
            *(float2*)(C + (size_t)(row + 8) * N + col) = v1;
        }
    }
}

// ---------------------------------------------------------------------------
// Flash attention fp16 (m16n8k16 + ldmatrix), causal.
// 64 q-rows, 128 threads / 4 warps (16 q-rows each). fp32 in/out.
// Q/K/V converted fp32->fp16 in staging stores. P direct c-frag -> a-frag.
// Structure (syncs, prefetch, heavy-first) identical to R7.
// Smem: Ks 64x72 halves (also Q staging) + Vs 64x72 = 18432 B static.
// ---------------------------------------------------------------------------
#define KSTH 72   // halves; rows 144 B (16-aligned for ldmatrix)

__global__ void __launch_bounds__(128)
attn_kernel(const float* __restrict__ qkv, float* __restrict__ out)
{
    __shared__ __half Ks[64 * KSTH];   // Q staging, then K tiles
    __shared__ __half Vs[64 * KSTH];

    const int tid  = threadIdx.x;
    const int w    = tid >> 5;
    const int lane = tid & 31;
    const int g    = lane >> 2;
    const int t    = lane & 3;
    const int r8   = lane & 7;
    const int j1   = (lane >> 3) & 1;
    const int j2   = (lane >> 4) & 1;
    const int h    = blockIdx.y;
    const int qb   = gridDim.x - 1 - blockIdx.x;   // heavy tiles first
    const int q0   = qb * 64;
    const int rA   = 16 * w + g;
    const float scale = 0.125f;

    const uint32_t ks_b = smem_u32(Ks);
    const uint32_t vs_b = smem_u32(Vs);

    const int kv_rr = tid >> 4;          // 0..7 (+8*i)
    const int kv_d4 = (tid & 15) << 2;   // 0..60

    // ---- Stage Q (scaled, fp16) into Ks region ----
#pragma unroll
    for (int i = 0; i < 8; i++) {
        int idx = tid + i * 128;
        int rr = idx >> 4;
        int d4 = (idx & 15) << 2;
        float4 v = *(const float4*)(qkv + (size_t)(q0 + rr) * QKV_N + h * HDIM + d4);
        uint2 hv = make_uint2(pack2(v.x * scale, v.y * scale),
                              pack2(v.z * scale, v.w * scale));
        *(uint2*)(Ks + rr * KSTH + d4) = hv;
    }
    __syncthreads();

    // ---- Q fragments: A-operand, rows 16w..16w+15, k blocks of 16 ----
    uint32_t qf[4][4];
    {
        uint32_t qbase = ks_b + (((16 * w + 8 * j1 + r8) * KSTH) + 8 * j2) * 2;
#pragma unroll
        for (int ks = 0; ks < 4; ks++)
            ldsm_x4(qf[ks], qbase + ks * 32);    // +16 halves per k block
    }
    __syncthreads();   // Q staging consumed; Ks free for K tiles

    // ---- K/V tile loaders (fp32 gmem -> fp16 smem) ----
    auto ldK = [&](int k0, float4 rk[8]) {
#pragma unroll
        for (int i = 0; i < 8; i++)
            rk[i] = *(const float4*)(qkv + (size_t)(k0 + kv_rr + 8 * i) * QKV_N
                                     + C_EMB + h * HDIM + kv_d4);
    };
    auto ldV = [&](int k0, float4 rv[8]) {
#pragma unroll
        for (int i = 0; i < 8; i++)
            rv[i] = *(const float4*)(qkv + (size_t)(k0 + kv_rr + 8 * i) * QKV_N
                                     + 2 * C_EMB + h * HDIM + kv_d4);
    };
    auto stK = [&](const float4 rk[8]) {
#pragma unroll
        for (int i = 0; i < 8; i++) {
            uint2 hv = make_uint2(pack2(rk[i].x, rk[i].y), pack2(rk[i].z, rk[i].w));
            *(uint2*)(Ks + (kv_rr + 8 * i) * KSTH + kv_d4) = hv;
        }
    };
    auto stV = [&](const float4 rv[8]) {
#pragma unroll
        for (int i = 0; i < 8; i++) {
            uint2 hv = make_uint2(pack2(rv[i].x, rv[i].y), pack2(rv[i].z, rv[i].w));
            *(uint2*)(Vs + (kv_rr + 8 * i) * KSTH + kv_d4) = hv;
        }
    };

    // ---- Prologue: tile 0 ----
    {
        float4 r0[8];
        ldK(0, r0); stK(r0);
        ldV(0, r0); stV(r0);
    }
    __syncthreads();

    // ldmatrix bases: K (B-op, rows=n(kv), cols=k(d)); V (B-op trans, rows=k(kv), cols=n(d))
    const uint32_t kS = ks_b + (((8 * j2 + r8) * KSTH) + 8 * j1) * 2;
    const uint32_t vS = vs_b + (((8 * j1 + r8) * KSTH) + 8 * j2) * 2;

    float o[8][4];
#pragma unroll
    for (int nb = 0; nb < 8; nb++)
#pragma unroll
        for (int j = 0; j < 4; j++) o[nb][j] = 0.f;
    float mA = -1e30f, mB = -1e30f, lA = 0.f, lB = 0.f;

    for (int kb = 0; kb <= qb; kb++) {
        const bool more = kb < qb;

        float4 rpf[8];
        if (more) ldK(64 * (kb + 1), rpf);

        // ---- S = Q K^T (fp16 mma, k16 steps) ----
        float s[8][4];
#pragma unroll
        for (int nb = 0; nb < 8; nb++)
#pragma unroll
            for (int j = 0; j < 4; j++) s[nb][j] = 0.f;

#pragma unroll
        for (int ks = 0; ks < 4; ks++) {
#pragma unroll
            for (int p = 0; p < 4; p++) {
                uint32_t b[4];
                ldsm_x4(b, kS + (p * 16 * KSTH + ks * 16) * 2);
                mma_f16(s[2 * p],     qf[ks], b[0], b[1]);
                mma_f16(s[2 * p + 1], qf[ks], b[2], b[3]);
            }
        }

        if (kb == qb) {   // diagonal tile: causal mask
            const int rowB = rA + 8;
#pragma unroll
            for (int nb = 0; nb < 8; nb++) {
                int c0 = 8 * nb + 2 * t;
                if (c0     > rA)   s[nb][0] = -1e30f;
                if (c0 + 1 > rA)   s[nb][1] = -1e30f;
                if (c0     > rowB) s[nb][2] = -1e30f;
                if (c0 + 1 > rowB) s[nb][3] = -1e30f;
            }
        }

        // ---- Online softmax ----
        float mxA = s[0][0], mxB = s[0][2];
#pragma unroll
        for (int nb = 0; nb < 8; nb++) {
            mxA = fmaxf(mxA, fmaxf(s[nb][0], s[nb][1]));
            mxB = fmaxf(mxB, fmaxf(s[nb][2], s[nb][3]));
        }
        mxA = fmaxf(mxA, __shfl_xor_sync(0xffffffffu, mxA, 1));
        mxA = fmaxf(mxA, __shfl_xor_sync(0xffffffffu, mxA, 2));
        mxB = fmaxf(mxB, __shfl_xor_sync(0xffffffffu, mxB, 1));
        mxB = fmaxf(mxB, __shfl_xor_sync(0xffffffffu, mxB, 2));

        float nmA = fmaxf(mA, mxA), nmB = fmaxf(mB, mxB);
        float corrA = __expf(mA - nmA), corrB = __expf(mB - nmB);
        mA = nmA; mB = nmB;
        lA *= corrA; lB *= corrB;

#pragma unroll
        for (int nb = 0; nb < 8; nb++) {
            s[nb][0] = __expf(s[nb][0] - mA); lA += s[nb][0];
            s[nb][1] = __expf(s[nb][1] - mA); lA += s[nb][1];
            s[nb][2] = __expf(s[nb][2] - mB); lB += s[nb][2];
            s[nb][3] = __expf(s[nb][3] - mB); lB += s[nb][3];
            o[nb][0] *= corrA; o[nb][1] *= corrA;
            o[nb][2] *= corrB; o[nb][3] *= corrB;
        }

        __syncthreads();          // all warps done reading Ks
        if (more) {
            stK(rpf);             // K(kb+1) -> Ks
            ldV(64 * (kb + 1), rpf);
        }

        // ---- P fragments: direct c-frag -> a-frag (no shuffles) ----
        uint32_t pfr[4][4];
#pragma unroll
        for (int ks = 0; ks < 4; ks++) {
            pfr[ks][0] = pack2(s[2 * ks][0],     s[2 * ks][1]);
            pfr[ks][1] = pack2(s[2 * ks][2],     s[2 * ks][3]);
            pfr[ks][2] = pack2(s[2 * ks + 1][0], s[2 * ks + 1][1]);
            pfr[ks][3] = pack2(s[2 * ks + 1][2], s[2 * ks + 1][3]);
        }

        // ---- O += P V ----
#pragma unroll
        for (int ks = 0; ks < 4; ks++) {
#pragma unroll
            for (int p = 0; p < 4; p++) {
                uint32_t b[4];
                ldsm_x4_t(b, vS + (ks * 16 * KSTH + p * 16) * 2);
                mma_f16(o[2 * p],     pfr[ks], b[0], b[1]);
                mma_f16(o[2 * p + 1], pfr[ks], b[2], b[3]);
            }
        }

        __syncthreads();          // all warps done reading Vs
        if (more) stV(rpf);       // V(kb+1) -> Vs
    }

    // ---- Finalize (fp32 out) ----
    lA += __shfl_xor_sync(0xffffffffu, lA, 1);
    lA += __shfl_xor_sync(0xffffffffu, lA, 2);
    lB += __shfl_xor_sync(0xffffffffu, lB, 1);
    lB += __shfl_xor_sync(0xffffffffu, lB, 2);
    float invA = 1.f / lA, invB = 1.f / lB;

    const int row = q0 + rA;
#pragma unroll
    for (int nb = 0; nb < 8; nb++) {
        int col = h * HDIM + 8 * nb + 2 * t;
        float2 va = make_float2(o[nb][0] * invA, o[nb][1] * invA);
        float2 vb = make_float2(o[nb][2] * invB, o[nb][3] * invB);
        *(float2*)(out + (size_t)row * C_EMB + col)       = va;
        *(float2*)(out + (size_t)(row + 8) * C_EMB + col) = vb;
    }
}

// ---------------------------------------------------------------------------
// Launch
// ---------------------------------------------------------------------------
extern "C" void kernel_launch(void* const* d_in, const int* in_sizes, int n_in,
                              void* d_out, int out_size)
{
    const float* x      = (const float*)d_in[0];
    const float* W_attn = (const float*)d_in[1];
    const float* b_attn = (const float*)d_in[2];
    const float* W_proj = (const float*)d_in[3];
    const float* b_proj = (const float*)d_in[4];
    float* out = (float*)d_out;

    float* qkv = nullptr;
    float* att = nullptr;
    float* wpt = nullptr;
    cudaGetSymbolAddress((void**)&qkv, g_qkv);
    cudaGetSymbolAddress((void**)&att, g_att);
    cudaGetSymbolAddress((void**)&wpt, g_wpt);

    // 0) W_proj^T
    transpose768<<<dim3(C_EMB / 32, C_EMB / 32), dim3(32, 8)>>>(W_proj, wpt);

    // 1) qkv = x @ W_attn + b_attn  (tf32, unchanged)
    gemm_tf32<2><<<dim3(QKV_N / GBN, T_SEQ / 128), 256>>>(
        x, W_attn, b_attn, qkv, T_SEQ, QKV_N, C_EMB);

    // 2) flash attention (fp16 mma + ldmatrix)
    attn_kernel<<<dim3(T_SEQ / 64, NHEAD), 128>>>(qkv, att);

    // 3) out = att @ W_proj^T + b_proj  (tf32, unchanged)
    gemm_tf32<1><<<dim3(C_EMB / GBN, T_SEQ / 64), 256>>>(
        att, wpt, b_proj, out, T_SEQ, C_EMB, C_EMB);
}

// round 10
// speedup vs baseline: 2.4533x; 1.4737x over previous
#include <cuda_runtime.h>
#include <cuda_fp16.h>
#include <math.h>
#include <stdint.h>

// ---------------------------------------------------------------------------
// Shapes (fixed)
// ---------------------------------------------------------------------------
#define T_SEQ   4096
#define C_EMB   768
#define NHEAD   12
#define HDIM    64
#define QKV_N   (3 * C_EMB)   // 2304

// Scratch (no cudaMalloc allowed)
__device__ __half g_qkv[T_SEQ * QKV_N];     // fp16 qkv (Q pre-scaled)
__device__ __half g_att[T_SEQ * C_EMB];     // fp16 attention out
__device__ __half g_wa16[C_EMB * QKV_N];    // W_attn fp16 [k][n]
__device__ __half g_wpt16[C_EMB * C_EMB];   // W_proj^T fp16 [k][n]

// ---------------------------------------------------------------------------
// helpers
// ---------------------------------------------------------------------------
__device__ __forceinline__ uint32_t smem_u32(const void* p) {
    uint32_t a;
    asm("{ .reg .u64 t; cvta.to.shared.u64 t, %1; cvt.u32.u64 %0, t; }"
        : "=r"(a) : "l"(p));
    return a;
}

__device__ __forceinline__ uint32_t pack2(float x, float y) {
    __half2 h = __float22half2_rn(make_float2(x, y));
    return *reinterpret_cast<uint32_t*>(&h);
}

__device__ __forceinline__ void mma_f16(float c[4], const uint32_t a[4],
                                        uint32_t b0, uint32_t b1) {
    asm volatile(
        "mma.sync.aligned.m16n8k16.row.col.f32.f16.f16.f32 "
        "{%0,%1,%2,%3}, {%4,%5,%6,%7}, {%8,%9}, {%0,%1,%2,%3};"
        : "+f"(c[0]), "+f"(c[1]), "+f"(c[2]), "+f"(c[3])
        : "r"(a[0]), "r"(a[1]), "r"(a[2]), "r"(a[3]), "r"(b0), "r"(b1));
}

__device__ __forceinline__ void ldsm_x4(uint32_t r[4], uint32_t addr) {
    asm volatile("ldmatrix.sync.aligned.m8n8.x4.shared.b16 {%0,%1,%2,%3}, [%4];"
                 : "=r"(r[0]), "=r"(r[1]), "=r"(r[2]), "=r"(r[3]) : "r"(addr));
}
__device__ __forceinline__ void ldsm_x4_t(uint32_t r[4], uint32_t addr) {
    asm volatile("ldmatrix.sync.aligned.m8n8.x4.trans.shared.b16 {%0,%1,%2,%3}, [%4];"
                 : "=r"(r[0]), "=r"(r[1]), "=r"(r[2]), "=r"(r[3]) : "r"(addr));
}

// ---------------------------------------------------------------------------
// Prep kernels
// ---------------------------------------------------------------------------
__global__ void w_to_half(const float* __restrict__ in,
                          __half* __restrict__ out, int n)
{
    int i = (blockIdx.x * 256 + threadIdx.x) * 4;
    if (i < n) {
        float4 v = *(const float4*)(in + i);
        uint2 h = make_uint2(pack2(v.x, v.y), pack2(v.z, v.w));
        *(uint2*)(out + i) = h;
    }
}

// W_proj [n][k] fp32 -> out [k][n] fp16  (768x768)
__global__ void wproj_t_half(const float* __restrict__ in,
                             __half* __restrict__ out)
{
    __shared__ float t[32][33];
    int x = blockIdx.x * 32 + threadIdx.x;
    int y0 = blockIdx.y * 32;
#pragma unroll
    for (int j = 0; j < 32; j += 8)
        t[threadIdx.y + j][threadIdx.x] = in[(size_t)(y0 + threadIdx.y + j) * C_EMB + x];
    __syncthreads();
#pragma unroll
    for (int j = 0; j < 32; j += 8)
        out[(size_t)(blockIdx.x * 32 + threadIdx.y + j) * C_EMB + y0 + threadIdx.x]
            = __float2half(t[threadIdx.x][threadIdx.y + j]);
}

// ---------------------------------------------------------------------------
// fp16 GEMM: C[M,N] = A[M,K] @ B[K,N] + bias[N]    (B fp16 [k][n])
// CTA tile (64*MI)x128, k-step 32, 256 threads / 8 warps, warp (16*MI)x64.
// A via ldmatrix.x4, B via ldmatrix.x4.trans. Epilogue *0.125 for n0<qcols.
// ---------------------------------------------------------------------------
#define ASTH 40    // As row stride (halves): 80B rows, conflict-free ldmatrix
#define BSTH 136   // Bs row stride (halves): 272B rows, conflict-free ldmatrix

template <bool A_HALF, bool C_HALF, int MI>
__global__ void __launch_bounds__(256)
gemm_f16(const void* __restrict__ Av, const __half* __restrict__ B,
         const float* __restrict__ bias, void* __restrict__ Cv,
         int M, int N, int K, int qcols)
{
    __shared__ __align__(16) __half As[64 * MI][ASTH];
    __shared__ __align__(16) __half Bs[32][BSTH];

    const int tid  = threadIdx.x;
    const int w    = tid >> 5;
    const int lane = tid & 31;
    const int g    = lane >> 2;
    const int t    = lane & 3;
    const int r8   = lane & 7;
    const int j1   = (lane >> 3) & 1;
    const int j2   = (lane >> 4) & 1;
    const int wm   = (w & 3) * 16 * MI;
    const int wn   = (w >> 2) * 64;
    const int m0   = blockIdx.y * 64 * MI;
    const int n0   = blockIdx.x * 128;

    const float osc = (n0 < qcols) ? 0.125f : 1.0f;

    const uint32_t as_b = smem_u32(As);
    const uint32_t bs_b = smem_u32(Bs);
    const uint32_t a_base = as_b + ((wm + 8 * j1 + r8) * ASTH + 8 * j2) * 2;
    const uint32_t b_base = bs_b + ((8 * j1 + r8) * BSTH + wn + 8 * j2) * 2;

    const float* Af = (const float*)Av;
    const __half* Ah = (const __half*)Av;

    // Prefetch registers
    float4 raF[2 * MI];   // fp32-A path: 64*MI rows x 8 float4/row / 256 thr
    uint4  raH[MI];       // fp16-A path: 64*MI rows x 4 uint4/row / 256 thr
    uint4  rb[2];         // B: 32 rows x 16 uint4/row / 256 thr

    auto load_tile = [&](int k0) {
        if (A_HALF) {
#pragma unroll
            for (int i = 0; i < MI; i++) {
                int idx = tid + i * 256;
                int rr = idx >> 2;             // 0 .. 64*MI-1
                int c8 = (idx & 3) * 8;        // 0,8,16,24
                raH[i] = *(const uint4*)(Ah + (size_t)(m0 + rr) * K + k0 + c8);
            }
        } else {
#pragma unroll
            for (int i = 0; i < 2 * MI; i++) {
                int idx = tid + i * 256;
                int rr = idx >> 3;             // 0 .. 64*MI-1
                int c4 = (idx & 7) * 4;        // 0..28
                raF[i] = *(const float4*)(Af + (size_t)(m0 + rr) * K + k0 + c4);
            }
        }
#pragma unroll
        for (int i = 0; i < 2; i++) {
            int idx = tid + i * 256;
            int rr = idx >> 4;                 // 0..31
            int c8 = (idx & 15) * 8;           // 0..120
            rb[i] = *(const uint4*)(B + (size_t)(k0 + rr) * N + n0 + c8);
        }
    };
    auto store_tile = [&]() {
        if (A_HALF) {
#pragma unroll
            for (int i = 0; i < MI; i++) {
                int idx = tid + i * 256;
                int rr = idx >> 2;
                int c8 = (idx & 3) * 8;
                *(uint4*)&As[rr][c8] = raH[i];
            }
        } else {
#pragma unroll
            for (int i = 0; i < 2 * MI; i++) {
                int idx = tid + i * 256;
                int rr = idx >> 3;
                int c4 = (idx & 7) * 4;
                uint2 h = make_uint2(pack2(raF[i].x, raF[i].y),
                                     pack2(raF[i].z, raF[i].w));
                *(uint2*)&As[rr][c4] = h;
            }
        }
#pragma unroll
        for (int i = 0; i < 2; i++) {
            int idx = tid + i * 256;
            int rr = idx >> 4;
            int c8 = (idx & 15) * 8;
            *(uint4*)&Bs[rr][c8] = rb[i];
        }
    };

    float acc[MI][8][4];
#pragma unroll
    for (int mi = 0; mi < MI; mi++)
#pragma unroll
        for (int ni = 0; ni < 8; ni++)
#pragma unroll
            for (int j = 0; j < 4; j++) acc[mi][ni][j] = 0.f;

    load_tile(0);
    store_tile();
    __syncthreads();

    for (int k0 = 0; k0 < K; k0 += 32) {
        const bool more = (k0 + 32) < K;
        if (more) load_tile(k0 + 32);

#pragma unroll
        for (int ks = 0; ks < 2; ks++) {
            uint32_t af[MI][4];
#pragma unroll
            for (int mi = 0; mi < MI; mi++)
                ldsm_x4(af[mi], a_base + (mi * 16 * ASTH + ks * 16) * 2);
#pragma unroll
            for (int p = 0; p < 4; p++) {
                uint32_t b[4];
                ldsm_x4_t(b, b_base + (ks * 16 * BSTH + p * 16) * 2);
#pragma unroll
                for (int mi = 0; mi < MI; mi++) {
                    mma_f16(acc[mi][2 * p],     af[mi], b[0], b[1]);
                    mma_f16(acc[mi][2 * p + 1], af[mi], b[2], b[3]);
                }
            }
        }
        __syncthreads();
        if (more) { store_tile(); __syncthreads(); }
    }

    // Epilogue
#pragma unroll
    for (int mi = 0; mi < MI; mi++) {
        int row = m0 + wm + 16 * mi + g;
#pragma unroll
        for (int ni = 0; ni < 8; ni++) {
            int col = n0 + wn + 8 * ni + 2 * t;
            float2 bv = *(const float2*)(bias + col);
            float v0x = (acc[mi][ni][0] + bv.x) * osc;
            float v0y = (acc[mi][ni][1] + bv.y) * osc;
            float v1x = (acc[mi][ni][2] + bv.x) * osc;
            float v1y = (acc[mi][ni][3] + bv.y) * osc;
            if (C_HALF) {
                __half* C = (__half*)Cv;
                *(uint32_t*)(C + (size_t)row * N + col)       = pack2(v0x, v0y);
                *(uint32_t*)(C + (size_t)(row + 8) * N + col) = pack2(v1x, v1y);
            } else {
                float* C = (float*)Cv;
                *(float2*)(C + (size_t)row * N + col)       = make_float2(v0x, v0y);
                *(float2*)(C + (size_t)(row + 8) * N + col) = make_float2(v1x, v1y);
            }
        }
    }
}

// ---------------------------------------------------------------------------
// Flash attention fp16 (m16n8k16 + ldmatrix), causal — structure from R9,
// now fp16 in/out (Q pre-scaled in qkv GEMM epilogue).
// 64 q-rows, 128 threads / 4 warps. Smem 18 KB.
// ---------------------------------------------------------------------------
#define KSTH 72   // halves; rows 144 B

__global__ void __launch_bounds__(128)
attn_kernel(const __half* __restrict__ qkv, __half* __restrict__ out)
{
    __shared__ __align__(16) __half Ks[64 * KSTH];   // Q staging, then K tiles
    __shared__ __align__(16) __half Vs[64 * KSTH];

    const int tid  = threadIdx.x;
    const int w    = tid >> 5;
    const int lane = tid & 31;
    const int g    = lane >> 2;
    const int t    = lane & 3;
    const int r8   = lane & 7;
    const int j1   = (lane >> 3) & 1;
    const int j2   = (lane >> 4) & 1;
    const int h    = blockIdx.y;
    const int qb   = gridDim.x - 1 - blockIdx.x;   // heavy tiles first
    const int q0   = qb * 64;
    const int rA   = 16 * w + g;

    const uint32_t ks_b = smem_u32(Ks);
    const uint32_t vs_b = smem_u32(Vs);

    // Gap-free tile mapping: 64 rows x 64 halves = 512 uint4; 128 thr x 4.
    // idx = tid + i*128 ; rr = idx>>3 (0..63) ; c8 = (idx&7)*8 (0..56).

    // ---- Stage Q into Ks ----
#pragma unroll
    for (int i = 0; i < 4; i++) {
        int idx = tid + i * 128;
        int rr = idx >> 3;
        int c8 = (idx & 7) * 8;
        *(uint4*)(Ks + rr * KSTH + c8) =
            *(const uint4*)(qkv + (size_t)(q0 + rr) * QKV_N + h * HDIM + c8);
    }
    __syncthreads();

    // ---- Q fragments ----
    uint32_t qf[4][4];
    {
        uint32_t qbase = ks_b + (((16 * w + 8 * j1 + r8) * KSTH) + 8 * j2) * 2;
#pragma unroll
        for (int ks = 0; ks < 4; ks++)
            ldsm_x4(qf[ks], qbase + ks * 32);
    }
    __syncthreads();   // Q staging consumed

    // ---- K/V loaders ----
    auto ldKV = [&](int k0, int which, uint4 r[4]) {
#pragma unroll
        for (int i = 0; i < 4; i++) {
            int idx = tid + i * 128;
            int rr = idx >> 3;
            int c8 = (idx & 7) * 8;
            r[i] = *(const uint4*)(qkv + (size_t)(k0 + rr) * QKV_N
                                   + which * C_EMB + h * HDIM + c8);
        }
    };
    auto stT = [&](__half* dst, const uint4 r[4]) {
#pragma unroll
        for (int i = 0; i < 4; i++) {
            int idx = tid + i * 128;
            int rr = idx >> 3;
            int c8 = (idx & 7) * 8;
            *(uint4*)(dst + rr * KSTH + c8) = r[i];
        }
    };

    // Prologue: tile 0
    {
        uint4 r0[4];
        ldKV(0, 1, r0); stT(Ks, r0);
        ldKV(0, 2, r0); stT(Vs, r0);
    }
    __syncthreads();

    const uint32_t kS = ks_b + (((8 * j2 + r8) * KSTH) + 8 * j1) * 2;
    const uint32_t vS = vs_b + (((8 * j1 + r8) * KSTH) + 8 * j2) * 2;

    float o[8][4];
#pragma unroll
    for (int nb = 0; nb < 8; nb++)
#pragma unroll
        for (int j = 0; j < 4; j++) o[nb][j] = 0.f;
    float mA = -1e30f, mB = -1e30f, lA = 0.f, lB = 0.f;

    for (int kb = 0; kb <= qb; kb++) {
        const bool more = kb < qb;

        uint4 rpf[4];
        if (more) ldKV(64 * (kb + 1), 1, rpf);

        // ---- S = Q K^T ----
        float s[8][4];
#pragma unroll
        for (int nb = 0; nb < 8; nb++)
#pragma unroll
            for (int j = 0; j < 4; j++) s[nb][j] = 0.f;

#pragma unroll
        for (int ks = 0; ks < 4; ks++) {
#pragma unroll
            for (int p = 0; p < 4; p++) {
                uint32_t b[4];
                ldsm_x4(b, kS + (p * 16 * KSTH + ks * 16) * 2);
                mma_f16(s[2 * p],     qf[ks], b[0], b[1]);
                mma_f16(s[2 * p + 1], qf[ks], b[2], b[3]);
            }
        }

        if (kb == qb) {   // diagonal tile: causal mask
            const int rowB = rA + 8;
#pragma unroll
            for (int nb = 0; nb < 8; nb++) {
                int c0 = 8 * nb + 2 * t;
                if (c0     > rA)   s[nb][0] = -1e30f;
                if (c0 + 1 > rA)   s[nb][1] = -1e30f;
                if (c0     > rowB) s[nb][2] = -1e30f;
                if (c0 + 1 > rowB) s[nb][3] = -1e30f;
            }
        }

        // ---- Online softmax ----
        float mxA = s[0][0], mxB = s[0][2];
#pragma unroll
        for (int nb = 0; nb < 8; nb++) {
            mxA = fmaxf(mxA, fmaxf(s[nb][0], s[nb][1]));
            mxB = fmaxf(mxB, fmaxf(s[nb][2], s[nb][3]));
        }
        mxA = fmaxf(mxA, __shfl_xor_sync(0xffffffffu, mxA, 1));
        mxA = fmaxf(mxA, __shfl_xor_sync(0xffffffffu, mxA, 2));
        mxB = fmaxf(mxB, __shfl_xor_sync(0xffffffffu, mxB, 1));
        mxB = fmaxf(mxB, __shfl_xor_sync(0xffffffffu, mxB, 2));

        float nmA = fmaxf(mA, mxA), nmB = fmaxf(mB, mxB);
        float corrA = __expf(mA - nmA), corrB = __expf(mB - nmB);
        mA = nmA; mB = nmB;
        lA *= corrA; lB *= corrB;

#pragma unroll
        for (int nb = 0; nb < 8; nb++) {
            s[nb][0] = __expf(s[nb][0] - mA); lA += s[nb][0];
            s[nb][1] = __expf(s[nb][1] - mA); lA += s[nb][1];
            s[nb][2] = __expf(s[nb][2] - mB); lB += s[nb][2];
            s[nb][3] = __expf(s[nb][3] - mB); lB += s[nb][3];
            o[nb][0] *= corrA; o[nb][1] *= corrA;
            o[nb][2] *= corrB; o[nb][3] *= corrB;
        }

        __syncthreads();          // all warps done reading Ks
        if (more) {
            stT(Ks, rpf);         // K(kb+1)
            ldKV(64 * (kb + 1), 2, rpf);
        }

        // ---- P fragments (direct c-frag -> a-frag) ----
        uint32_t pfr[4][4];
#pragma unroll
        for (int ks = 0; ks < 4; ks++) {
            pfr[ks][0] = pack2(s[2 * ks][0],     s[2 * ks][1]);
            pfr[ks][1] = pack2(s[2 * ks][2],     s[2 * ks][3]);
            pfr[ks][2] = pack2(s[2 * ks + 1][0], s[2 * ks + 1][1]);
            pfr[ks][3] = pack2(s[2 * ks + 1][2], s[2 * ks + 1][3]);
        }

        // ---- O += P V ----
#pragma unroll
        for (int ks = 0; ks < 4; ks++) {
#pragma unroll
            for (int p = 0; p < 4; p++) {
                uint32_t b[4];
                ldsm_x4_t(b, vS + (ks * 16 * KSTH + p * 16) * 2);
                mma_f16(o[2 * p],     pfr[ks], b[0], b[1]);
                mma_f16(o[2 * p + 1], pfr[ks], b[2], b[3]);
            }
        }

        __syncthreads();          // all warps done reading Vs
        if (more) stT(Vs, rpf);   // V(kb+1)
    }

    // ---- Finalize (fp16 out) ----
    lA += __shfl_xor_sync(0xffffffffu, lA, 1);
    lA += __shfl_xor_sync(0xffffffffu, lA, 2);
    lB += __shfl_xor_sync(0xffffffffu, lB, 1);
    lB += __shfl_xor_sync(0xffffffffu, lB, 2);
    float invA = 1.f / lA, invB = 1.f / lB;

    const int row = q0 + rA;
#pragma unroll
    for (int nb = 0; nb < 8; nb++) {
        int col = h * HDIM + 8 * nb + 2 * t;
        *(uint32_t*)(out + (size_t)row * C_EMB + col)
            = pack2(o[nb][0] * invA, o[nb][1] * invA);
        *(uint32_t*)(out + (size_t)(row + 8) * C_EMB + col)
            = pack2(o[nb][2] * invB, o[nb][3] * invB);
    }
}

// ---------------------------------------------------------------------------
// Launch
// ---------------------------------------------------------------------------
extern "C" void kernel_launch(void* const* d_in, const int* in_sizes, int n_in,
                              void* d_out, int out_size)
{
    const float* x      = (const float*)d_in[0];
    const float* W_attn = (const float*)d_in[1];
    const float* b_attn = (const float*)d_in[2];
    const float* W_proj = (const float*)d_in[3];
    const float* b_proj = (const float*)d_in[4];
    float* out = (float*)d_out;

    __half *qkv, *att, *wa16, *wpt16;
    cudaGetSymbolAddress((void**)&qkv,   g_qkv);
    cudaGetSymbolAddress((void**)&att,   g_att);
    cudaGetSymbolAddress((void**)&wa16,  g_wa16);
    cudaGetSymbolAddress((void**)&wpt16, g_wpt16);

    // 0a) W_attn -> fp16 [k][n]
    w_to_half<<<(C_EMB * QKV_N) / 1024, 256>>>(W_attn, wa16, C_EMB * QKV_N);
    // 0b) W_proj -> fp16 transposed [k][n]
    wproj_t_half<<<dim3(C_EMB / 32, C_EMB / 32), dim3(32, 8)>>>(W_proj, wpt16);

    // 1) qkv = (x @ W_attn + b) fp16, Q columns pre-scaled by 0.125
    gemm_f16<false, true, 2><<<dim3(QKV_N / 128, T_SEQ / 128), 256>>>(
        x, wa16, b_attn, qkv, T_SEQ, QKV_N, C_EMB, C_EMB);

    // 2) flash attention (fp16 in/out)
    attn_kernel<<<dim3(T_SEQ / 64, NHEAD), 128>>>(qkv, att);

    // 3) out = att @ W_proj^T + b_proj (fp32 out)
    gemm_f16<true, false, 1><<<dim3(C_EMB / 128, T_SEQ / 64), 256>>>(
        att, wpt16, b_proj, out, T_SEQ, C_EMB, C_EMB, 0);
}

// round 11
// speedup vs baseline: 2.4749x; 1.0088x over previous
#include <cuda_runtime.h>
#include <cuda_fp16.h>
#include <math.h>
#include <stdint.h>

// ---------------------------------------------------------------------------
// Shapes (fixed)
// ---------------------------------------------------------------------------
#define T_SEQ   4096
#define C_EMB   768
#define NHEAD   12
#define HDIM    64
#define QKV_N   (3 * C_EMB)   // 2304

// Scratch (no cudaMalloc allowed)
__device__ __half g_qkv[T_SEQ * QKV_N];     // fp16 qkv (Q pre-scaled)
__device__ __half g_att[T_SEQ * C_EMB];     // fp16 attention out
__device__ __half g_wa16[C_EMB * QKV_N];    // W_attn fp16 [k][n]
__device__ __half g_wpt16[C_EMB * C_EMB];   // W_proj^T fp16 [k][n]

// ---------------------------------------------------------------------------
// helpers
// ---------------------------------------------------------------------------
__device__ __forceinline__ uint32_t smem_u32(const void* p) {
    uint32_t a;
    asm("{ .reg .u64 t; cvta.to.shared.u64 t, %1; cvt.u32.u64 %0, t; }"
        : "=r"(a) : "l"(p));
    return a;
}

__device__ __forceinline__ uint32_t pack2(float x, float y) {
    __half2 h = __float22half2_rn(make_float2(x, y));
    return *reinterpret_cast<uint32_t*>(&h);
}

__device__ __forceinline__ void mma_f16(float c[4], const uint32_t a[4],
                                        uint32_t b0, uint32_t b1) {
    asm volatile(
        "mma.sync.aligned.m16n8k16.row.col.f32.f16.f16.f32 "
        "{%0,%1,%2,%3}, {%4,%5,%6,%7}, {%8,%9}, {%0,%1,%2,%3};"
        : "+f"(c[0]), "+f"(c[1]), "+f"(c[2]), "+f"(c[3])
        : "r"(a[0]), "r"(a[1]), "r"(a[2]), "r"(a[3]), "r"(b0), "r"(b1));
}

__device__ __forceinline__ void ldsm_x4(uint32_t r[4], uint32_t addr) {
    asm volatile("ldmatrix.sync.aligned.m8n8.x4.shared.b16 {%0,%1,%2,%3}, [%4];"
                 : "=r"(r[0]), "=r"(r[1]), "=r"(r[2]), "=r"(r[3]) : "r"(addr));
}
__device__ __forceinline__ void ldsm_x4_t(uint32_t r[4], uint32_t addr) {
    asm volatile("ldmatrix.sync.aligned.m8n8.x4.trans.shared.b16 {%0,%1,%2,%3}, [%4];"
                 : "=r"(r[0]), "=r"(r[1]), "=r"(r[2]), "=r"(r[3]) : "r"(addr));
}

__device__ __forceinline__ void cp16(uint32_t dst, const void* src) {
    asm volatile("cp.async.cg.shared.global [%0], [%1], 16;"
                 :: "r"(dst), "l"(src) : "memory");
}
__device__ __forceinline__ void cp_commit() {
    asm volatile("cp.async.commit_group;" ::: "memory");
}
template <int N>
__device__ __forceinline__ void cp_wait() {
    asm volatile("cp.async.wait_group %0;" :: "n"(N) : "memory");
}

// ---------------------------------------------------------------------------
// Prep kernels
// ---------------------------------------------------------------------------
__global__ void w_to_half(const float* __restrict__ in,
                          __half* __restrict__ out, int n)
{
    int i = (blockIdx.x * 256 + threadIdx.x) * 4;
    if (i < n) {
        float4 v = *(const float4*)(in + i);
        uint2 h = make_uint2(pack2(v.x, v.y), pack2(v.z, v.w));
        *(uint2*)(out + i) = h;
    }
}

__global__ void wproj_t_half(const float* __restrict__ in,
                             __half* __restrict__ out)
{
    __shared__ float t[32][33];
    int x = blockIdx.x * 32 + threadIdx.x;
    int y0 = blockIdx.y * 32;
#pragma unroll
    for (int j = 0; j < 32; j += 8)
        t[threadIdx.y + j][threadIdx.x] = in[(size_t)(y0 + threadIdx.y + j) * C_EMB + x];
    __syncthreads();
#pragma unroll
    for (int j = 0; j < 32; j += 8)
        out[(size_t)(blockIdx.x * 32 + threadIdx.y + j) * C_EMB + y0 + threadIdx.x]
            = __float2half(t[threadIdx.x][threadIdx.y + j]);
}

// ---------------------------------------------------------------------------
// fp16 GEMM (verbatim R10): C[M,N] = A[M,K] @ B[K,N] + bias[N]
// ---------------------------------------------------------------------------
#define ASTH 40
#define BSTH 136

template <bool A_HALF, bool C_HALF, int MI>
__global__ void __launch_bounds__(256)
gemm_f16(const void* __restrict__ Av, const __half* __restrict__ B,
         const float* __restrict__ bias, void* __restrict__ Cv,
         int M, int N, int K, int qcols)
{
    __shared__ __align__(16) __half As[64 * MI][ASTH];
    __shared__ __align__(16) __half Bs[32][BSTH];

    const int tid  = threadIdx.x;
    const int w    = tid >> 5;
    const int lane = tid & 31;
    const int g    = lane >> 2;
    const int t    = lane & 3;
    const int r8   = lane & 7;
    const int j1   = (lane >> 3) & 1;
    const int j2   = (lane >> 4) & 1;
    const int wm   = (w & 3) * 16 * MI;
    const int wn   = (w >> 2) * 64;
    const int m0   = blockIdx.y * 64 * MI;
    const int n0   = blockIdx.x * 128;

    const float osc = (n0 < qcols) ? 0.125f : 1.0f;

    const uint32_t as_b = smem_u32(As);
    const uint32_t bs_b = smem_u32(Bs);
    const uint32_t a_base = as_b + ((wm + 8 * j1 + r8) * ASTH + 8 * j2) * 2;
    const uint32_t b_base = bs_b + ((8 * j1 + r8) * BSTH + wn + 8 * j2) * 2;

    const float* Af = (const float*)Av;
    const __half* Ah = (const __half*)Av;

    float4 raF[2 * MI];
    uint4  raH[MI];
    uint4  rb[2];

    auto load_tile = [&](int k0) {
        if (A_HALF) {
#pragma unroll
            for (int i = 0; i < MI; i++) {
                int idx = tid + i * 256;
                int rr = idx >> 2;
                int c8 = (idx & 3) * 8;
                raH[i] = *(const uint4*)(Ah + (size_t)(m0 + rr) * K + k0 + c8);
            }
        } else {
#pragma unroll
            for (int i = 0; i < 2 * MI; i++) {
                int idx = tid + i * 256;
                int rr = idx >> 3;
                int c4 = (idx & 7) * 4;
                raF[i] = *(const float4*)(Af + (size_t)(m0 + rr) * K + k0 + c4);
            }
        }
#pragma unroll
        for (int i = 0; i < 2; i++) {
            int idx = tid + i * 256;
            int rr = idx >> 4;
            int c8 = (idx & 15) * 8;
            rb[i] = *(const uint4*)(B + (size_t)(k0 + rr) * N + n0 + c8);
        }
    };
    auto store_tile = [&]() {
        if (A_HALF) {
#pragma unroll
            for (int i = 0; i < MI; i++) {
                int idx = tid + i * 256;
                int rr = idx >> 2;
                int c8 = (idx & 3) * 8;
                *(uint4*)&As[rr][c8] = raH[i];
            }
        } else {
#pragma unroll
            for (int i = 0; i < 2 * MI; i++) {
                int idx = tid + i * 256;
                int rr = idx >> 3;
                int c4 = (idx & 7) * 4;
                uint2 h = make_uint2(pack2(raF[i].x, raF[i].y),
                                     pack2(raF[i].z, raF[i].w));
                *(uint2*)&As[rr][c4] = h;
            }
        }
#pragma unroll
        for (int i = 0; i < 2; i++) {
            int idx = tid + i * 256;
            int rr = idx >> 4;
            int c8 = (idx & 15) * 8;
            *(uint4*)&Bs[rr][c8] = rb[i];
        }
    };

    float acc[MI][8][4];
#pragma unroll
    for (int mi = 0; mi < MI; mi++)
#pragma unroll
        for (int ni = 0; ni < 8; ni++)
#pragma unroll
            for (int j = 0; j < 4; j++) acc[mi][ni][j] = 0.f;

    load_tile(0);
    store_tile();
    __syncthreads();

    for (int k0 = 0; k0 < K; k0 += 32) {
        const bool more = (k0 + 32) < K;
        if (more) load_tile(k0 + 32);

#pragma unroll
        for (int ks = 0; ks < 2; ks++) {
            uint32_t af[MI][4];
#pragma unroll
            for (int mi = 0; mi < MI; mi++)
                ldsm_x4(af[mi], a_base + (mi * 16 * ASTH + ks * 16) * 2);
#pragma unroll
            for (int p = 0; p < 4; p++) {
                uint32_t b[4];
                ldsm_x4_t(b, b_base + (ks * 16 * BSTH + p * 16) * 2);
#pragma unroll
                for (int mi = 0; mi < MI; mi++) {
                    mma_f16(acc[mi][2 * p],     af[mi], b[0], b[1]);
                    mma_f16(acc[mi][2 * p + 1], af[mi], b[2], b[3]);
                }
            }
        }
        __syncthreads();
        if (more) { store_tile(); __syncthreads(); }
    }

#pragma unroll
    for (int mi = 0; mi < MI; mi++) {
        int row = m0 + wm + 16 * mi + g;
#pragma unroll
        for (int ni = 0; ni < 8; ni++) {
            int col = n0 + wn + 8 * ni + 2 * t;
            float2 bv = *(const float2*)(bias + col);
            float v0x = (acc[mi][ni][0] + bv.x) * osc;
            float v0y = (acc[mi][ni][1] + bv.y) * osc;
            float v1x = (acc[mi][ni][2] + bv.x) * osc;
            float v1y = (acc[mi][ni][3] + bv.y) * osc;
            if (C_HALF) {
                __half* C = (__half*)Cv;
                *(uint32_t*)(C + (size_t)row * N + col)       = pack2(v0x, v0y);
                *(uint32_t*)(C + (size_t)(row + 8) * N + col) = pack2(v1x, v1y);
            } else {
                float* C = (float*)Cv;
                *(float2*)(C + (size_t)row * N + col)       = make_float2(v0x, v0y);
                *(float2*)(C + (size_t)(row + 8) * N + col) = make_float2(v1x, v1y);
            }
        }
    }
}

// ---------------------------------------------------------------------------
// Flash attention fp16, cp.async double-buffered K/V, causal.
// 64 q-rows, 128 threads / 4 warps. Smem 4 x 9216 B = 36864 B.
// __launch_bounds__(128,4): cap regs at 128 for 4 CTAs/SM.
// ---------------------------------------------------------------------------
#define KSTH 72          // halves per row (144 B)
#define TBUF (64 * KSTH) // halves per tile buffer

__global__ void __launch_bounds__(128, 4)
attn_kernel(const __half* __restrict__ qkv, __half* __restrict__ out)
{
    __shared__ __align__(16) __half SM[4][TBUF];  // K0,V0,K1,V1

    const int tid  = threadIdx.x;
    const int w    = tid >> 5;
    const int lane = tid & 31;
    const int g    = lane >> 2;
    const int t    = lane & 3;
    const int r8   = lane & 7;
    const int j1   = (lane >> 3) & 1;
    const int j2   = (lane >> 4) & 1;
    const int h    = blockIdx.y;
    const int qb   = gridDim.x - 1 - blockIdx.x;   // heavy tiles first
    const int q0   = qb * 64;
    const int rA   = 16 * w + g;

    const uint32_t sm_b = smem_u32(SM);

    // Gap-free mapping: idx = tid + i*128; rr = idx>>3 (0..63); c8 = (idx&7)*8
    const int m_rr = tid >> 3;
    const int m_c8 = (tid & 7) * 8;

    // ---- Stage Q into buffer 0 (plain stores), extract fragments ----
#pragma unroll
    for (int i = 0; i < 4; i++) {
        int rr = m_rr + 16 * i;
        *(uint4*)(SM[0] + rr * KSTH + m_c8) =
            *(const uint4*)(qkv + (size_t)(q0 + rr) * QKV_N + h * HDIM + m_c8);
    }
    __syncthreads();

    uint32_t qf[4][4];
    {
        uint32_t qbase = sm_b + (((16 * w + 8 * j1 + r8) * KSTH) + 8 * j2) * 2;
#pragma unroll
        for (int ks = 0; ks < 4; ks++)
            ldsm_x4(qf[ks], qbase + ks * 32);
    }
    __syncthreads();   // Q staging consumed; buffer 0 free

    // ---- cp.async tile issue: K into SM[2*buf], V into SM[2*buf+1] ----
    auto issue_tile = [&](int kb, int buf) {
        const __half* kbase = qkv + (size_t)(kb * 64 + m_rr) * QKV_N + C_EMB + h * HDIM + m_c8;
        uint32_t kd = sm_b + ((2 * buf) * TBUF + m_rr * KSTH + m_c8) * 2;
        uint32_t vd = kd + TBUF * 2;
#pragma unroll
        for (int i = 0; i < 4; i++) {
            cp16(kd + 16 * i * KSTH * 2, kbase + (size_t)(16 * i) * QKV_N);
            cp16(vd + 16 * i * KSTH * 2, kbase + (size_t)(16 * i) * QKV_N + C_EMB);
        }
        cp_commit();
    };

    // Prologue: tiles 0 and 1
    issue_tile(0, 0);
    if (qb >= 1) issue_tile(1, 1);

    float o[8][4];
#pragma unroll
    for (int nb = 0; nb < 8; nb++)
#pragma unroll
        for (int j = 0; j < 4; j++) o[nb][j] = 0.f;
    float mA = -1e30f, mB = -1e30f, lA = 0.f, lB = 0.f;

    for (int kb = 0; kb <= qb; kb++) {
        const int buf = kb & 1;
        const bool more = kb < qb;

        if (more) cp_wait<1>(); else cp_wait<0>();
        __syncthreads();          // tile kb visible to all warps

        const uint32_t kS = sm_b + ((2 * buf) * TBUF + (8 * j2 + r8) * KSTH + 8 * j1) * 2;
        const uint32_t vS = sm_b + ((2 * buf + 1) * TBUF + (8 * j1 + r8) * KSTH + 8 * j2) * 2;

        // ---- S = Q K^T ----
        float s[8][4];
#pragma unroll
        for (int nb = 0; nb < 8; nb++)
#pragma unroll
            for (int j = 0; j < 4; j++) s[nb][j] = 0.f;

#pragma unroll
        for (int ks = 0; ks < 4; ks++) {
#pragma unroll
            for (int p = 0; p < 4; p++) {
                uint32_t b[4];
                ldsm_x4(b, kS + (p * 16 * KSTH + ks * 16) * 2);
                mma_f16(s[2 * p],     qf[ks], b[0], b[1]);
                mma_f16(s[2 * p + 1], qf[ks], b[2], b[3]);
            }
        }

        if (kb == qb) {   // diagonal tile: causal mask
            const int rowB = rA + 8;
#pragma unroll
            for (int nb = 0; nb < 8; nb++) {
                int c0 = 8 * nb + 2 * t;
                if (c0     > rA)   s[nb][0] = -1e30f;
                if (c0 + 1 > rA)   s[nb][1] = -1e30f;
                if (c0     > rowB) s[nb][2] = -1e30f;
                if (c0 + 1 > rowB) s[nb][3] = -1e30f;
            }
        }

        // ---- Online softmax ----
        float mxA = s[0][0], mxB = s[0][2];
#pragma unroll
        for (int nb = 0; nb < 8; nb++) {
            mxA = fmaxf(mxA, fmaxf(s[nb][0], s[nb][1]));
            mxB = fmaxf(mxB, fmaxf(s[nb][2], s[nb][3]));
        }
        mxA = fmaxf(mxA, __shfl_xor_sync(0xffffffffu, mxA, 1));
        mxA = fmaxf(mxA, __shfl_xor_sync(0xffffffffu, mxA, 2));
        mxB = fmaxf(mxB, __shfl_xor_sync(0xffffffffu, mxB, 1));
        mxB = fmaxf(mxB, __shfl_xor_sync(0xffffffffu, mxB, 2));

        float nmA = fmaxf(mA, mxA), nmB = fmaxf(mB, mxB);
        float corrA = __expf(mA - nmA), corrB = __expf(mB - nmB);
        mA = nmA; mB = nmB;
        lA *= corrA; lB *= corrB;

#pragma unroll
        for (int nb = 0; nb < 8; nb++) {
            s[nb][0] = __expf(s[nb][0] - mA); lA += s[nb][0];
            s[nb][1] = __expf(s[nb][1] - mA); lA += s[nb][1];
            s[nb][2] = __expf(s[nb][2] - mB); lB += s[nb][2];
            s[nb][3] = __expf(s[nb][3] - mB); lB += s[nb][3];
            o[nb][0] *= corrA; o[nb][1] *= corrA;
            o[nb][2] *= corrB; o[nb][3] *= corrB;
        }

        // ---- P fragments (direct c-frag -> a-frag) ----
        uint32_t pfr[4][4];
#pragma unroll
        for (int ks = 0; ks < 4; ks++) {
            pfr[ks][0] = pack2(s[2 * ks][0],     s[2 * ks][1]);
            pfr[ks][1] = pack2(s[2 * ks][2],     s[2 * ks][3]);
            pfr[ks][2] = pack2(s[2 * ks + 1][0], s[2 * ks + 1][1]);
            pfr[ks][3] = pack2(s[2 * ks + 1][2], s[2 * ks + 1][3]);
        }

        // ---- O += P V ----
#pragma unroll
        for (int ks = 0; ks < 4; ks++) {
#pragma unroll
            for (int p = 0; p < 4; p++) {
                uint32_t b[4];
                ldsm_x4_t(b, vS + (ks * 16 * KSTH + p * 16) * 2);
                mma_f16(o[2 * p],     pfr[ks], b[0], b[1]);
                mma_f16(o[2 * p + 1], pfr[ks], b[2], b[3]);
            }
        }

        __syncthreads();          // all warps done with buffer `buf`
        if (kb + 2 <= qb) issue_tile(kb + 2, buf);
    }

    // ---- Finalize (fp16 out) ----
    lA += __shfl_xor_sync(0xffffffffu, lA, 1);
    lA += __shfl_xor_sync(0xffffffffu, lA, 2);
    lB += __shfl_xor_sync(0xffffffffu, lB, 1);
    lB += __shfl_xor_sync(0xffffffffu, lB, 2);
    float invA = 1.f / lA, invB = 1.f / lB;

    const int row = q0 + rA;
#pragma unroll
    for (int nb = 0; nb < 8; nb++) {
        int col = h * HDIM + 8 * nb + 2 * t;
        *(uint32_t*)(out + (size_t)row * C_EMB + col)
            = pack2(o[nb][0] * invA, o[nb][1] * invA);
        *(uint32_t*)(out + (size_t)(row + 8) * C_EMB + col)
            = pack2(o[nb][2] * invB, o[nb][3] * invB);
    }
}

// ---------------------------------------------------------------------------
// Launch
// ---------------------------------------------------------------------------
extern "C" void kernel_launch(void* const* d_in, const int* in_sizes, int n_in,
                              void* d_out, int out_size)
{
    const float* x      = (const float*)d_in[0];
    const float* W_attn = (const float*)d_in[1];
    const float* b_attn = (const float*)d_in[2];
    const float* W_proj = (const float*)d_in[3];
    const float* b_proj = (const float*)d_in[4];
    float* out = (float*)d_out;

    __half *qkv, *att, *wa16, *wpt16;
    cudaGetSymbolAddress((void**)&qkv,   g_qkv);
    cudaGetSymbolAddress((void**)&att,   g_att);
    cudaGetSymbolAddress((void**)&wa16,  g_wa16);
    cudaGetSymbolAddress((void**)&wpt16, g_wpt16);

    // 0) weight prep
    w_to_half<<<(C_EMB * QKV_N) / 1024, 256>>>(W_attn, wa16, C_EMB * QKV_N);
    wproj_t_half<<<dim3(C_EMB / 32, C_EMB / 32), dim3(32, 8)>>>(W_proj, wpt16);

    // 1) qkv = (x @ W_attn + b) fp16, Q pre-scaled by 0.125
    gemm_f16<false, true, 2><<<dim3(QKV_N / 128, T_SEQ / 128), 256>>>(
        x, wa16, b_attn, qkv, T_SEQ, QKV_N, C_EMB, C_EMB);

    // 2) flash attention (fp16, cp.async pipelined)
    attn_kernel<<<dim3(T_SEQ / 64, NHEAD), 128>>>(qkv, att);

    // 3) out = att @ W_proj^T + b_proj (fp32 out)
    gemm_f16<true, false, 1><<<dim3(C_EMB / 128, T_SEQ / 64), 256>>>(
        att, wpt16, b_proj, out, T_SEQ, C_EMB, C_EMB, 0);
}